// round 13
// baseline (speedup 1.0000x reference)
#include <cuda_runtime.h>
#include <cuda_bf16.h>
#include <cstdint>

// ============================================================================
// SparseConvNet_Triplane v8: stride-1 convs as implicit GEMM on
// mma.sync.m16n8k8.tf32 with 3xTF32 error compensation (hi/lo split).
// Stride-2 convs + epilogues remain the proven scalar path (v7).
// (resubmit: R12 was an infra failure, kernel never ran)
// ============================================================================

#define EPSV 1e-3f

static constexpr int N0 = 64 * 64 * 64;
static constexpr int N1 = 32 * 32 * 32;
static constexpr int N2 = 16 * 16 * 16;
static constexpr int NPTS = 65536;

static constexpr int PD0 = 66, PD0_3 = PD0 * PD0 * PD0;
static constexpr int PD1 = 34, PD1_3 = PD1 * PD1 * PD1;
static constexpr int PD2 = 18, PD2_3 = PD2 * PD2 * PD2;

// weight segments (float counts), scalar layout [ci][k][co]
static constexpr int O_W0A = 0;
static constexpr int O_W0B = O_W0A + 16 * 32 * 27;
static constexpr int O_WD0 = O_W0B + 32 * 32 * 27;
static constexpr int O_W1A = O_WD0 + 32 * 32 * 27;
static constexpr int O_W1B = O_W1A + 32 * 64 * 27;
static constexpr int O_WD1 = O_W1B + 64 * 64 * 27;
static constexpr int O_W2A = O_WD1 + 64 * 128 * 27;
static constexpr int O_W2B = O_W2A + 128 * 128 * 27;
static constexpr int O_W2C = O_W2B + 128 * 128 * 27;
static constexpr int WT_TOTAL = O_W2C + 128 * 128 * 27;

// fused BN scale/shift segments
static constexpr int OB_0A = 0;
static constexpr int OB_0B = OB_0A + 2 * 32;
static constexpr int OB_D0 = OB_0B + 2 * 32;
static constexpr int OB_1A = OB_D0 + 2 * 32;
static constexpr int OB_1B = OB_1A + 2 * 64;
static constexpr int OB_D1 = OB_1B + 2 * 64;
static constexpr int OB_2A = OB_D1 + 2 * 128;
static constexpr int OB_2B = OB_2A + 2 * 128;
static constexpr int OB_2C = OB_2B + 2 * 128;

// static scratch; halos of padded buffers never written -> stay 0
__device__ __align__(16) float g_xm[16 * PD0_3];
__device__ __align__(16) float g_A0[32 * PD0_3];
__device__ __align__(16) float g_B0[32 * PD0_3];
__device__ __align__(16) float g_A1[64 * PD1_3];
__device__ __align__(16) float g_B1[64 * PD1_3];
__device__ __align__(16) float g_A2[128 * PD2_3];
__device__ __align__(16) float g_B2[128 * PD2_3];
__device__ __align__(16) float g_part[2097152];
__device__ float g_m0[N0];
__device__ float g_m1[N1];
__device__ float g_m2[N2];
__device__ __align__(16) float g_wt[WT_TOTAL];
__device__ __align__(16) float4 g_twt[WT_TOTAL / 2];   // packed tf32 hi/lo B tiles
__device__ __align__(16) float g_bnf[OB_2C + 2 * 128];
__device__ __align__(16) float g_planes[3 * 16 * 16 * 128];
__device__ int g_mmode;

// ----------------------------------------------------------------------------
// tf32 helpers
// ----------------------------------------------------------------------------
__device__ __forceinline__ uint32_t tf32_of(float a) {
    uint32_t r;
    asm("cvt.rna.tf32.f32 %0, %1;" : "=r"(r) : "f"(a));
    return r;
}
__device__ __forceinline__ void split_tf32(float a, uint32_t& hi, uint32_t& lo) {
    hi = tf32_of(a);
    lo = tf32_of(a - __uint_as_float(hi));
}
__device__ __forceinline__ void mma_tf32(float* c, const uint32_t* a, uint32_t b0, uint32_t b1) {
    asm("mma.sync.aligned.m16n8k8.row.col.f32.tf32.tf32.f32 "
        "{%0,%1,%2,%3}, {%4,%5,%6,%7}, {%8,%9}, {%0,%1,%2,%3};"
        : "+f"(c[0]), "+f"(c[1]), "+f"(c[2]), "+f"(c[3])
        : "r"(a[0]), "r"(a[1]), "r"(a[2]), "r"(a[3]), "r"(b0), "r"(b1));
}

// ----------------------------------------------------------------------------
// merged prep: scalar wt transpose + BN fusion + packed tf32 hi/lo tiles
// twt blk layout per layer: [k][ci/8][co/8] -> 32 lanes x float4(hi0,hi1,lo0,lo1)
//   lane (gid=lane>>2, tg=lane&3): b0 = W[ci0+tg][co0+gid], b1 = W[ci0+tg+4][co0+gid]
// ----------------------------------------------------------------------------
__global__ void prep_k(const float* __restrict__ w0a, const float* __restrict__ w0b,
                       const float* __restrict__ wd0, const float* __restrict__ w1a,
                       const float* __restrict__ w1b, const float* __restrict__ wd1,
                       const float* __restrict__ w2a, const float* __restrict__ w2b,
                       const float* __restrict__ w2c,
                       const float* __restrict__ b0a, const float* __restrict__ b0b,
                       const float* __restrict__ bd0, const float* __restrict__ b1a,
                       const float* __restrict__ b1b, const float* __restrict__ bd1,
                       const float* __restrict__ b2a, const float* __restrict__ b2b,
                       const float* __restrict__ b2c,
                       float* __restrict__ wt, float* __restrict__ bnf,
                       float4* __restrict__ twt) {
    int i = blockIdx.x * blockDim.x + threadIdx.x;
    if (i < WT_TOTAL) {
        const float* src; int off, cin, cout;
        if      (i < O_W0B) { src = w0a; off = O_W0A; cin = 16;  cout = 32; }
        else if (i < O_WD0) { src = w0b; off = O_W0B; cin = 32;  cout = 32; }
        else if (i < O_W1A) { src = wd0; off = O_WD0; cin = 32;  cout = 32; }
        else if (i < O_W1B) { src = w1a; off = O_W1A; cin = 32;  cout = 64; }
        else if (i < O_WD1) { src = w1b; off = O_W1B; cin = 64;  cout = 64; }
        else if (i < O_W2A) { src = wd1; off = O_WD1; cin = 64;  cout = 128; }
        else if (i < O_W2B) { src = w2a; off = O_W2A; cin = 128; cout = 128; }
        else if (i < O_W2C) { src = w2b; off = O_W2B; cin = 128; cout = 128; }
        else                { src = w2c; off = O_W2C; cin = 128; cout = 128; }
        int r = i - off;
        int co = r % cout;
        int k  = (r / cout) % 27;
        int ci = r / (cout * 27);
        wt[i] = src[(co * cin + ci) * 27 + k];
    } else if (i < WT_TOTAL + 736) {
        int j = i - WT_TOTAL;
        const float* bn; int off, C, c;
        if      (j < 32)  { bn = b0a; off = OB_0A; C = 32;  c = j; }
        else if (j < 64)  { bn = b0b; off = OB_0B; C = 32;  c = j - 32; }
        else if (j < 96)  { bn = bd0; off = OB_D0; C = 32;  c = j - 64; }
        else if (j < 160) { bn = b1a; off = OB_1A; C = 64;  c = j - 96; }
        else if (j < 224) { bn = b1b; off = OB_1B; C = 64;  c = j - 160; }
        else if (j < 352) { bn = bd1; off = OB_D1; C = 128; c = j - 224; }
        else if (j < 480) { bn = b2a; off = OB_2A; C = 128; c = j - 352; }
        else if (j < 608) { bn = b2b; off = OB_2B; C = 128; c = j - 480; }
        else              { bn = b2c; off = OB_2C; C = 128; c = j - 608; }
        float g = bn[c], b = bn[C + c], mu = bn[2 * C + c], v = bn[3 * C + c];
        float s = g * rsqrtf(v + EPSV);
        bnf[off + 2 * c] = s;
        bnf[off + 2 * c + 1] = b - s * mu;
    } else {
        int i2 = i - (WT_TOTAL + 736);            // float4 index in twt
        if (i2 >= WT_TOTAL / 2) return;
        int ff = 2 * i2;                           // float-offset equivalent
        const float* src; int off, cin, cout;
        if      (ff < O_W0B) { src = w0a; off = O_W0A; cin = 16;  cout = 32; }
        else if (ff < O_WD0) { src = w0b; off = O_W0B; cin = 32;  cout = 32; }
        else if (ff < O_W1A) { src = wd0; off = O_WD0; cin = 32;  cout = 32; }
        else if (ff < O_W1B) { src = w1a; off = O_W1A; cin = 32;  cout = 64; }
        else if (ff < O_WD1) { src = w1b; off = O_W1B; cin = 64;  cout = 64; }
        else if (ff < O_W2A) { src = wd1; off = O_WD1; cin = 64;  cout = 128; }
        else if (ff < O_W2B) { src = w2a; off = O_W2A; cin = 128; cout = 128; }
        else if (ff < O_W2C) { src = w2b; off = O_W2B; cin = 128; cout = 128; }
        else                 { src = w2c; off = O_W2C; cin = 128; cout = 128; }
        int r4 = i2 - off / 2;
        int lane = r4 & 31;
        int blk = r4 >> 5;
        int ntt = cout / 8, cs = cin / 8;
        int t = blk % ntt;
        int s = (blk / ntt) % cs;
        int kk = blk / (ntt * cs);
        int tg = lane & 3, gid = lane >> 2;
        int ci = s * 8 + tg;
        int co = t * 8 + gid;
        float w00 = src[(co * cin + ci) * 27 + kk];
        float w01 = src[(co * cin + ci + 4) * 27 + kk];
        uint32_t h0, l0, h1, l1;
        split_tf32(w00, h0, l0);
        split_tf32(w01, h1, l1);
        twt[i2] = make_float4(__uint_as_float(h0), __uint_as_float(h1),
                              __uint_as_float(l0), __uint_as_float(l1));
    }
}

// ----------------------------------------------------------------------------
// mask dtype probe (mode 0=u8 bool, 1=i32 bool, 2=f32, 3=bf16)
// ----------------------------------------------------------------------------
__global__ void probe_k(const unsigned char* __restrict__ b) {
    __shared__ int s_off1, s_big;
    if (threadIdx.x == 0) { s_off1 = 0; s_big = 0; }
    __syncthreads();
    int off1 = 0, big = 0;
    for (int i = threadIdx.x; i < 16384; i += blockDim.x) {
        unsigned char b0 = b[4 * i + 0], b1 = b[4 * i + 1];
        unsigned char b2 = b[4 * i + 2], b3 = b[4 * i + 3];
        if (b1) off1++;
        if (b0 > 1 || b1 > 1 || b2 > 1 || b3 > 1) big++;
    }
    atomicAdd(&s_off1, off1);
    atomicAdd(&s_big, big);
    __syncthreads();
    if (threadIdx.x == 0)
        g_mmode = (s_big == 0) ? ((s_off1 > 0) ? 0 : 1) : ((s_off1 > 0) ? 3 : 2);
}

__device__ __forceinline__ float mask_at(const unsigned char* b, int v, int mode) {
    if (mode == 0) return b[v] ? 1.f : 0.f;
    if (mode == 1) return ((const int*)b)[v] ? 1.f : 0.f;
    if (mode == 2) return (((const float*)b)[v] != 0.f) ? 1.f : 0.f;
    return (__bfloat162float(((const __nv_bfloat16*)b)[v]) != 0.f) ? 1.f : 0.f;
}

__global__ void premask_k(const float* __restrict__ x, const unsigned char* __restrict__ mb,
                          float* __restrict__ xm, float* __restrict__ m0) {
    int v = blockIdx.x * blockDim.x + threadIdx.x;
    if (v >= N0) return;
    int mode = g_mmode;
    float m = mask_at(mb, v, mode);
    m0[v] = m;
    int xx = v & 63, yy = (v >> 6) & 63, zz = v >> 12;
    int pidx = ((zz + 1) * PD0 + (yy + 1)) * PD0 + (xx + 1);
#pragma unroll
    for (int ci = 0; ci < 16; ci++) xm[ci * PD0_3 + pidx] = x[ci * N0 + v] * m;
}

template <int DIN>
__global__ void down_k(const float* __restrict__ mi, float* __restrict__ mo) {
    constexpr int DOUT = DIN / 2;
    int id = blockIdx.x * blockDim.x + threadIdx.x;
    if (id >= DOUT * DOUT * DOUT) return;
    int x = id % DOUT, y = (id / DOUT) % DOUT, z = id / (DOUT * DOUT);
    float m = 0.f;
#pragma unroll
    for (int dz = -1; dz <= 1; dz++) {
        int zz = 2 * z + dz; if ((unsigned)zz >= DIN) continue;
#pragma unroll
        for (int dy = -1; dy <= 1; dy++) {
            int yy = 2 * y + dy; if ((unsigned)yy >= DIN) continue;
#pragma unroll
            for (int dx = -1; dx <= 1; dx++) {
                int xx = 2 * x + dx; if ((unsigned)xx >= DIN) continue;
                m = fmaxf(m, mi[(zz * DIN + yy) * DIN + xx]);
            }
        }
    }
    mo[id] = m;
}

// ----------------------------------------------------------------------------
// tensor-core stride-1 conv: implicit GEMM over 27 shifted taps, 3xTF32.
// CTA: 4 warps, each owns one 16-voxel m-tile of a 64-voxel row group.
// grid = (COUT/NCH, DIN/YR, DIN), YR = 64/DIN rows per CTA.
// ----------------------------------------------------------------------------
template <int CIN, int COUT, int DIN, int NCH>
__global__ __launch_bounds__(128) void tconv_k(const float* __restrict__ in,
                                               const float4* __restrict__ wb,
                                               const float* __restrict__ bnf,
                                               const float* __restrict__ mask,
                                               float* __restrict__ out) {
    constexpr int PDI = DIN + 2;
    constexpr int PDI3 = PDI * PDI * PDI;
    constexpr int PDO = DIN + 2;
    constexpr int PDO3 = PDI3;
    constexpr int TPR = DIN / 16;     // m-tiles per row
    constexpr int YR = 64 / DIN;      // rows per CTA
    constexpr int NT = NCH / 8;       // n-tiles per CTA
    constexpr int CS = CIN / 8;       // k8 steps per tap
    constexpr int NTT = COUT / 8;     // total n-tiles in twt layout

    const int warp = threadIdx.x >> 5, lane = threadIdx.x & 31;
    const int gid = lane >> 2, tg = lane & 3;
    const int nc = blockIdx.x;
    const int z = blockIdx.z;
    const int ym = blockIdx.y * YR + warp / TPR;
    const int xt = (warp % TPR) * 16;

    float c[NT][4];
#pragma unroll
    for (int t = 0; t < NT; t++)
#pragma unroll
        for (int j = 0; j < 4; j++) c[t][j] = 0.f;

    const float* inb = in + (size_t)tg * PDI3;

#pragma unroll 1
    for (int kk = 0; kk < 27; kk++) {
        int dz = kk / 9;
        int r9 = kk - dz * 9;
        int dy = r9 / 3;
        int dx = r9 - dy * 3;
        const float* ap = inb + ((z + dz) * PDI + (ym + dy)) * PDI + (xt + dx) + gid;
        const float4* bp = wb + ((size_t)kk * CS * NTT + (size_t)nc * NT) * 32 + lane;
#pragma unroll 4
        for (int s = 0; s < CS; s++) {
            float a0f = __ldg(ap);
            float a1f = __ldg(ap + 8);
            float a2f = __ldg(ap + 4 * PDI3);
            float a3f = __ldg(ap + 4 * PDI3 + 8);
            uint32_t ah[4], al[4];
            split_tf32(a0f, ah[0], al[0]);
            split_tf32(a1f, ah[1], al[1]);
            split_tf32(a2f, ah[2], al[2]);
            split_tf32(a3f, ah[3], al[3]);
#pragma unroll
            for (int t = 0; t < NT; t++) {
                float4 bb = __ldg(bp + t * 32);
                uint32_t bh0 = __float_as_uint(bb.x), bh1 = __float_as_uint(bb.y);
                uint32_t bl0 = __float_as_uint(bb.z), bl1 = __float_as_uint(bb.w);
                mma_tf32(c[t], ah, bh0, bh1);
                mma_tf32(c[t], ah, bl0, bl1);
                mma_tf32(c[t], al, bh0, bh1);
            }
            ap += (size_t)8 * PDI3;
            bp += NTT * 32;
        }
    }

    // fused BN + ReLU + mask epilogue (padded output)
    int voxu = (z * DIN + ym) * DIN + xt;
    float mv0 = mask[voxu + gid];
    float mv1 = mask[voxu + gid + 8];
    int pv = ((z + 1) * PDO + (ym + 1)) * PDO + (xt + 1) + gid;
#pragma unroll
    for (int t = 0; t < NT; t++) {
        int c0 = nc * NCH + t * 8 + 2 * tg;
        float4 b4 = *reinterpret_cast<const float4*>(bnf + 2 * c0);
        float* o0 = out + (size_t)c0 * PDO3 + pv;
        float* o1 = o0 + PDO3;
        o0[0] = fmaxf(fmaf(b4.x, c[t][0], b4.y), 0.f) * mv0;
        o1[0] = fmaxf(fmaf(b4.z, c[t][1], b4.w), 0.f) * mv0;
        o0[8] = fmaxf(fmaf(b4.x, c[t][2], b4.y), 0.f) * mv1;
        o1[8] = fmaxf(fmaf(b4.z, c[t][3], b4.w), 0.f) * mv1;
    }
}

// ----------------------------------------------------------------------------
// scalar conv (stride-2 layers) — unchanged v7
// ----------------------------------------------------------------------------
template <int CIN, int COUT, int STRIDE, int DIN, int SPLIT, int XT, int YT, int CH, bool FUSE>
__global__ __launch_bounds__(128, 4) void conv_k(const float* __restrict__ in,
                                                 const float* __restrict__ wt,
                                                 const float* __restrict__ bnf,
                                                 const float* __restrict__ mask,
                                                 float* __restrict__ out) {
    constexpr int DOUT = DIN / STRIDE;
    constexpr int PDI = DIN + 2;
    constexpr int PDI3 = PDI * PDI * PDI;
    constexpr int PDO = DOUT + 2;
    constexpr int PDO3 = PDO * PDO * PDO;
    constexpr int CHUNKS = COUT / CH;
    constexpr int CIB = CIN / SPLIT;
    constexpr int W = (XT - 1) * STRIDE + 3;
    constexpr int ROWS = (YT - 1) * STRIDE + 3;

    int tx = threadIdx.x, ty = threadIdx.y;
    int chunk = blockIdx.x % CHUNKS;
    int split = blockIdx.x / CHUNKS;
    int cb = chunk * CH;
    int y0 = (blockIdx.y * blockDim.y + ty) * YT;
    int z = blockIdx.z * blockDim.z + threadIdx.z;
    int x0 = XT * tx;

    float acc[YT * XT * CH];
#pragma unroll
    for (int i = 0; i < YT * XT * CH; i++) acc[i] = 0.f;

    const float* base = in + split * CIB * PDI3
                        + (z * STRIDE * PDI + y0 * STRIDE) * PDI + x0 * STRIDE;
    const float* wp = wt + (split * CIB * 27) * COUT + cb;

    for (int ci = 0; ci < CIB; ci++) {
#pragma unroll
        for (int dz = 0; dz < 3; dz++) {
            float v[ROWS][W];
#pragma unroll
            for (int r = 0; r < ROWS; r++) {
                const float* rp = base + (dz * PDI + r) * PDI;
                const float2* rp2 = reinterpret_cast<const float2*>(rp);
#pragma unroll
                for (int i = 0; i < W / 2; i++) {
                    float2 t = __ldg(rp2 + i);
                    v[r][2 * i] = t.x;
                    v[r][2 * i + 1] = t.y;
                }
                if (W & 1) v[r][W - 1] = __ldg(rp + W - 1);
            }
#pragma unroll
            for (int dy = 0; dy < 3; dy++)
#pragma unroll
                for (int dx = 0; dx < 3; dx++) {
                    const int k = (dz * 3 + dy) * 3 + dx;
                    const float4* w4 = reinterpret_cast<const float4*>(wp + k * COUT);
#pragma unroll
                    for (int j = 0; j < CH / 4; j++) {
                        float4 ww = __ldg(w4 + j);
#pragma unroll
                        for (int yt = 0; yt < YT; yt++)
#pragma unroll
                            for (int xt = 0; xt < XT; xt++) {
                                float a = v[yt * STRIDE + dy][xt * STRIDE + dx];
                                int o = (yt * XT + xt) * CH + 4 * j;
                                acc[o + 0] = fmaf(a, ww.x, acc[o + 0]);
                                acc[o + 1] = fmaf(a, ww.y, acc[o + 1]);
                                acc[o + 2] = fmaf(a, ww.z, acc[o + 2]);
                                acc[o + 3] = fmaf(a, ww.w, acc[o + 3]);
                            }
                    }
                }
        }
        base += PDI3;
        wp += 27 * COUT;
    }

    if (FUSE) {
#pragma unroll
        for (int yt = 0; yt < YT; yt++) {
            int voxu = (z * DOUT + y0 + yt) * DOUT + x0;
            float mm[XT];
#pragma unroll
            for (int xt = 0; xt < XT; xt++) mm[xt] = mask[voxu + xt];
            int pvox = ((z + 1) * PDO + (y0 + yt + 1)) * PDO + (x0 + 1);
#pragma unroll
            for (int i = 0; i < CH; i++) {
                int c = cb + i;
                float s = __ldg(bnf + 2 * c);
                float t = __ldg(bnf + 2 * c + 1);
#pragma unroll
                for (int xt = 0; xt < XT; xt++)
                    out[c * PDO3 + pvox + xt] =
                        fmaxf(fmaf(s, acc[(yt * XT + xt) * CH + i], t), 0.f) * mm[xt];
            }
        }
    } else {
        constexpr int N = DOUT * DOUT * DOUT;
#pragma unroll
        for (int yt = 0; yt < YT; yt++) {
            int vox = (z * DOUT + y0 + yt) * DOUT + x0;
#pragma unroll
            for (int i = 0; i < CH; i++) {
                int c = cb + i;
#pragma unroll
                for (int xt = 0; xt < XT; xt++)
                    out[(split * COUT + c) * N + vox + xt] = acc[(yt * XT + xt) * CH + i];
            }
        }
    }
}

// epilogue for split convs
template <int COUT, int DOUT, int SPLIT>
__global__ void epi_k(const float* __restrict__ part, const float* __restrict__ bnf,
                      const float* __restrict__ mask, float* __restrict__ out) {
    constexpr int N = DOUT * DOUT * DOUT;
    constexpr int PDO = DOUT + 2;
    constexpr int PDO3 = PDO * PDO * PDO;
    int id = blockIdx.x * blockDim.x + threadIdx.x;
    if (id >= COUT * N) return;
    int vox = id % N, c = id / N;
    float a = 0.f;
#pragma unroll
    for (int s = 0; s < SPLIT; s++) a += part[(s * COUT + c) * N + vox];
    float sc = __ldg(bnf + 2 * c), t = __ldg(bnf + 2 * c + 1);
    int x = vox % DOUT, y = (vox / DOUT) % DOUT, z = vox / (DOUT * DOUT);
    out[c * PDO3 + ((z + 1) * PDO + (y + 1)) * PDO + (x + 1)] =
        fmaxf(fmaf(sc, a, t), 0.f) * mask[vox];
}

// ----------------------------------------------------------------------------
// triplane means + sampler
// ----------------------------------------------------------------------------
__global__ void planes_k(const float* __restrict__ f, float* __restrict__ pl) {
    int id = blockIdx.x * blockDim.x + threadIdx.x;
    if (id >= 3 * 16 * 16 * 128) return;
    int c = id & 127;
    int rem = id >> 7;
    int b = rem & 15;
    int a = (rem >> 4) & 15;
    int t = rem >> 8;
    const float* fc = f + c * PD2_3;
    float s = 0.f;
    if (t == 0) {
#pragma unroll
        for (int z = 0; z < 16; z++) s += fc[((z + 1) * PD2 + (a + 1)) * PD2 + (b + 1)];
    } else if (t == 1) {
#pragma unroll
        for (int xx = 0; xx < 16; xx++) s += fc[((a + 1) * PD2 + (b + 1)) * PD2 + (xx + 1)];
    } else {
#pragma unroll
        for (int yy = 0; yy < 16; yy++) s += fc[((a + 1) * PD2 + (yy + 1)) * PD2 + (b + 1)];
    }
    pl[t * (16 * 16 * 128) + (a * 16 + b) * 128 + c] = s * (1.f / 16.f);
}

__device__ __forceinline__ float samp2d(const float* __restrict__ img, float gx, float gy, int c) {
    float ix = (gx + 1.f) * 0.5f * 15.f;
    float iy = (gy + 1.f) * 0.5f * 15.f;
    float x0f = floorf(ix), y0f = floorf(iy);
    int x0 = (int)x0f, y0 = (int)y0f;
    float wx = ix - x0f, wy = iy - y0f;
    float r = 0.f;
#pragma unroll
    for (int dy = 0; dy < 2; dy++)
#pragma unroll
        for (int dx = 0; dx < 2; dx++) {
            int xx = x0 + dx, yy = y0 + dy;
            float w = (dy ? wy : 1.f - wy) * (dx ? wx : 1.f - wx);
            bool ok = ((unsigned)xx < 16u) && ((unsigned)yy < 16u);
            int xc = min(max(xx, 0), 15), yc = min(max(yy, 0), 15);
            float v = __ldg(img + (yc * 16 + xc) * 128 + c);
            r += v * (ok ? w : 0.f);
        }
    return r;
}

__global__ void sample_k(const float* __restrict__ coords, const float* __restrict__ planes,
                         float* __restrict__ out) {
    constexpr int PTS = 16;
    int c = threadIdx.x;  // 128
    int p0 = blockIdx.x * PTS;
#pragma unroll 1
    for (int i = 0; i < PTS; i++) {
        int p = p0 + i;
        float c0 = __ldg(coords + 3 * p + 0);
        float c1 = __ldg(coords + 3 * p + 1);
        float c2 = __ldg(coords + 3 * p + 2);
        float s = samp2d(planes + 0 * (16 * 16 * 128), c0, c1, c)
                + samp2d(planes + 1 * (16 * 16 * 128), c1, c2, c)
                + samp2d(planes + 2 * (16 * 16 * 128), c0, c2, c);
        out[(size_t)p * 128 + c] = s;
    }
}

// ----------------------------------------------------------------------------
// launch — launch #4 is tconv0a (ncu target)
// ----------------------------------------------------------------------------
extern "C" void kernel_launch(void* const* d_in, const int* in_sizes, int n_in,
                              void* d_out, int out_size) {
    const float* x = (const float*)d_in[0];
    const unsigned char* mask = (const unsigned char*)d_in[1];
    const float* coords = (const float*)d_in[2];
    const float* w0a = (const float*)d_in[3];  const float* bn0a = (const float*)d_in[4];
    const float* w0b = (const float*)d_in[5];  const float* bn0b = (const float*)d_in[6];
    const float* wd0 = (const float*)d_in[7];  const float* bnd0 = (const float*)d_in[8];
    const float* w1a = (const float*)d_in[9];  const float* bn1a = (const float*)d_in[10];
    const float* w1b = (const float*)d_in[11]; const float* bn1b = (const float*)d_in[12];
    const float* wd1 = (const float*)d_in[13]; const float* bnd1 = (const float*)d_in[14];
    const float* w2a = (const float*)d_in[15]; const float* bn2a = (const float*)d_in[16];
    const float* w2b = (const float*)d_in[17]; const float* bn2b = (const float*)d_in[18];
    const float* w2c = (const float*)d_in[19]; const float* bn2c = (const float*)d_in[20];

    float *xm, *A0, *B0, *A1, *B1, *A2, *B2, *part, *m0, *m1, *m2, *wt, *bnf, *pl;
    float4* twt;
    cudaGetSymbolAddress((void**)&xm, g_xm);
    cudaGetSymbolAddress((void**)&A0, g_A0);
    cudaGetSymbolAddress((void**)&B0, g_B0);
    cudaGetSymbolAddress((void**)&A1, g_A1);
    cudaGetSymbolAddress((void**)&B1, g_B1);
    cudaGetSymbolAddress((void**)&A2, g_A2);
    cudaGetSymbolAddress((void**)&B2, g_B2);
    cudaGetSymbolAddress((void**)&part, g_part);
    cudaGetSymbolAddress((void**)&m0, g_m0);
    cudaGetSymbolAddress((void**)&m1, g_m1);
    cudaGetSymbolAddress((void**)&m2, g_m2);
    cudaGetSymbolAddress((void**)&wt, g_wt);
    cudaGetSymbolAddress((void**)&twt, g_twt);
    cudaGetSymbolAddress((void**)&bnf, g_bnf);
    cudaGetSymbolAddress((void**)&pl, g_planes);

    // 1-3: probe, merged prep (wt + bn + twt), premask
    probe_k<<<1, 256>>>(mask);
    int prtot = WT_TOTAL + 736 + WT_TOTAL / 2;
    prep_k<<<(prtot + 255) / 256, 256>>>(w0a, w0b, wd0, w1a, w1b, wd1, w2a, w2b, w2c,
                                         bn0a, bn0b, bnd0, bn1a, bn1b, bnd1, bn2a, bn2b, bn2c,
                                         wt, bnf, twt);
    premask_k<<<(N0 + 255) / 256, 256>>>(x, mask, xm, m0);

    // 4-6: tensor-core conv0a (ncu target), conv0b, scalar convd0
    tconv_k<16, 32, 64, 32><<<dim3(1, 64, 64), 128>>>(xm, twt + O_W0A / 2, bnf + OB_0A, m0, A0);
    tconv_k<32, 32, 64, 32><<<dim3(1, 64, 64), 128>>>(A0, twt + O_W0B / 2, bnf + OB_0B, m0, B0);
    conv_k<32, 32, 2, 64, 2, 2, 1, 16, false><<<dim3(4, 4, 32), dim3(16, 8)>>>(B0, wt + O_WD0, nullptr, nullptr, part);

    // 7-9: mask downsamples + epi_d0
    down_k<64><<<(N1 + 255) / 256, 256>>>(m0, m1);
    epi_k<32, 32, 2><<<(32 * N1 + 255) / 256, 256>>>(part, bnf + OB_D0, m1, A1);
    down_k<32><<<(N2 + 255) / 256, 256>>>(m1, m2);

    // 10-13: stage 1 @32^3 (tensor) + downsample 1 (scalar)
    tconv_k<32, 64, 32, 64><<<dim3(1, 16, 32), 128>>>(A1, twt + O_W1A / 2, bnf + OB_1A, m1, B1);
    tconv_k<64, 64, 32, 64><<<dim3(1, 16, 32), 128>>>(B1, twt + O_W1B / 2, bnf + OB_1B, m1, A1);
    conv_k<64, 128, 2, 32, 4, 2, 1, 16, false><<<dim3(32, 1, 16), dim3(8, 16)>>>(A1, wt + O_WD1, nullptr, nullptr, part);
    epi_k<128, 16, 4><<<(128 * N2 + 255) / 256, 256>>>(part, bnf + OB_D1, m2, A2);

    // 14-16: stage 2 @16^3 (tensor, fused — no split/epi needed)
    tconv_k<128, 128, 16, 32><<<dim3(4, 4, 16), 128>>>(A2, twt + O_W2A / 2, bnf + OB_2A, m2, B2);
    tconv_k<128, 128, 16, 32><<<dim3(4, 4, 16), 128>>>(B2, twt + O_W2B / 2, bnf + OB_2B, m2, A2);
    tconv_k<128, 128, 16, 32><<<dim3(4, 4, 16), 128>>>(A2, twt + O_W2C / 2, bnf + OB_2C, m2, B2);

    // 17-18: triplane + sample
    planes_k<<<(3 * 16 * 16 * 128 + 255) / 256, 256>>>(B2, pl);
    sample_k<<<NPTS / 16, 128>>>(coords, pl, (float*)d_out);
}

// round 14
// speedup vs baseline: 1.2418x; 1.2418x over previous
#include <cuda_runtime.h>
#include <cuda_bf16.h>
#include <cstdint>

// ============================================================================
// SparseConvNet_Triplane v9: tensor-core stride-1 convs (3xTF32) with split
// accumulators (hi / correction) for 1.5x ILP, incremental tap pointers,
// higher CTA counts on small layers. Stride-2 convs remain scalar (v7).
// ============================================================================

#define EPSV 1e-3f

static constexpr int N0 = 64 * 64 * 64;
static constexpr int N1 = 32 * 32 * 32;
static constexpr int N2 = 16 * 16 * 16;
static constexpr int NPTS = 65536;

static constexpr int PD0 = 66, PD0_3 = PD0 * PD0 * PD0;
static constexpr int PD1 = 34, PD1_3 = PD1 * PD1 * PD1;
static constexpr int PD2 = 18, PD2_3 = PD2 * PD2 * PD2;

// weight segments (float counts), scalar layout [ci][k][co]
static constexpr int O_W0A = 0;
static constexpr int O_W0B = O_W0A + 16 * 32 * 27;
static constexpr int O_WD0 = O_W0B + 32 * 32 * 27;
static constexpr int O_W1A = O_WD0 + 32 * 32 * 27;
static constexpr int O_W1B = O_W1A + 32 * 64 * 27;
static constexpr int O_WD1 = O_W1B + 64 * 64 * 27;
static constexpr int O_W2A = O_WD1 + 64 * 128 * 27;
static constexpr int O_W2B = O_W2A + 128 * 128 * 27;
static constexpr int O_W2C = O_W2B + 128 * 128 * 27;
static constexpr int WT_TOTAL = O_W2C + 128 * 128 * 27;

// fused BN scale/shift segments
static constexpr int OB_0A = 0;
static constexpr int OB_0B = OB_0A + 2 * 32;
static constexpr int OB_D0 = OB_0B + 2 * 32;
static constexpr int OB_1A = OB_D0 + 2 * 32;
static constexpr int OB_1B = OB_1A + 2 * 64;
static constexpr int OB_D1 = OB_1B + 2 * 64;
static constexpr int OB_2A = OB_D1 + 2 * 128;
static constexpr int OB_2B = OB_2A + 2 * 128;
static constexpr int OB_2C = OB_2B + 2 * 128;

// static scratch; halos of padded buffers never written -> stay 0
__device__ __align__(16) float g_xm[16 * PD0_3];
__device__ __align__(16) float g_A0[32 * PD0_3];
__device__ __align__(16) float g_B0[32 * PD0_3];
__device__ __align__(16) float g_A1[64 * PD1_3];
__device__ __align__(16) float g_B1[64 * PD1_3];
__device__ __align__(16) float g_A2[128 * PD2_3];
__device__ __align__(16) float g_B2[128 * PD2_3];
__device__ __align__(16) float g_part[2097152];
__device__ float g_m0[N0];
__device__ float g_m1[N1];
__device__ float g_m2[N2];
__device__ __align__(16) float g_wt[WT_TOTAL];
__device__ __align__(16) float4 g_twt[WT_TOTAL / 2];   // packed tf32 hi/lo B tiles
__device__ __align__(16) float g_bnf[OB_2C + 2 * 128];
__device__ __align__(16) float g_planes[3 * 16 * 16 * 128];
__device__ int g_mmode;

// ----------------------------------------------------------------------------
// tf32 helpers
// ----------------------------------------------------------------------------
__device__ __forceinline__ uint32_t tf32_of(float a) {
    uint32_t r;
    asm("cvt.rna.tf32.f32 %0, %1;" : "=r"(r) : "f"(a));
    return r;
}
__device__ __forceinline__ void split_tf32(float a, uint32_t& hi, uint32_t& lo) {
    hi = tf32_of(a);
    lo = tf32_of(a - __uint_as_float(hi));
}
__device__ __forceinline__ void mma_tf32(float* c, const uint32_t* a, uint32_t b0, uint32_t b1) {
    asm("mma.sync.aligned.m16n8k8.row.col.f32.tf32.tf32.f32 "
        "{%0,%1,%2,%3}, {%4,%5,%6,%7}, {%8,%9}, {%0,%1,%2,%3};"
        : "+f"(c[0]), "+f"(c[1]), "+f"(c[2]), "+f"(c[3])
        : "r"(a[0]), "r"(a[1]), "r"(a[2]), "r"(a[3]), "r"(b0), "r"(b1));
}

// ----------------------------------------------------------------------------
// merged prep: scalar wt transpose + BN fusion + packed tf32 hi/lo tiles
// twt blk layout per layer: [k][ci/8][co/8] -> 32 lanes x float4(hi0,hi1,lo0,lo1)
// ----------------------------------------------------------------------------
__global__ void prep_k(const float* __restrict__ w0a, const float* __restrict__ w0b,
                       const float* __restrict__ wd0, const float* __restrict__ w1a,
                       const float* __restrict__ w1b, const float* __restrict__ wd1,
                       const float* __restrict__ w2a, const float* __restrict__ w2b,
                       const float* __restrict__ w2c,
                       const float* __restrict__ b0a, const float* __restrict__ b0b,
                       const float* __restrict__ bd0, const float* __restrict__ b1a,
                       const float* __restrict__ b1b, const float* __restrict__ bd1,
                       const float* __restrict__ b2a, const float* __restrict__ b2b,
                       const float* __restrict__ b2c,
                       float* __restrict__ wt, float* __restrict__ bnf,
                       float4* __restrict__ twt) {
    int i = blockIdx.x * blockDim.x + threadIdx.x;
    if (i < WT_TOTAL) {
        const float* src; int off, cin, cout;
        if      (i < O_W0B) { src = w0a; off = O_W0A; cin = 16;  cout = 32; }
        else if (i < O_WD0) { src = w0b; off = O_W0B; cin = 32;  cout = 32; }
        else if (i < O_W1A) { src = wd0; off = O_WD0; cin = 32;  cout = 32; }
        else if (i < O_W1B) { src = w1a; off = O_W1A; cin = 32;  cout = 64; }
        else if (i < O_WD1) { src = w1b; off = O_W1B; cin = 64;  cout = 64; }
        else if (i < O_W2A) { src = wd1; off = O_WD1; cin = 64;  cout = 128; }
        else if (i < O_W2B) { src = w2a; off = O_W2A; cin = 128; cout = 128; }
        else if (i < O_W2C) { src = w2b; off = O_W2B; cin = 128; cout = 128; }
        else                { src = w2c; off = O_W2C; cin = 128; cout = 128; }
        int r = i - off;
        int co = r % cout;
        int k  = (r / cout) % 27;
        int ci = r / (cout * 27);
        wt[i] = src[(co * cin + ci) * 27 + k];
    } else if (i < WT_TOTAL + 736) {
        int j = i - WT_TOTAL;
        const float* bn; int off, C, c;
        if      (j < 32)  { bn = b0a; off = OB_0A; C = 32;  c = j; }
        else if (j < 64)  { bn = b0b; off = OB_0B; C = 32;  c = j - 32; }
        else if (j < 96)  { bn = bd0; off = OB_D0; C = 32;  c = j - 64; }
        else if (j < 160) { bn = b1a; off = OB_1A; C = 64;  c = j - 96; }
        else if (j < 224) { bn = b1b; off = OB_1B; C = 64;  c = j - 160; }
        else if (j < 352) { bn = bd1; off = OB_D1; C = 128; c = j - 224; }
        else if (j < 480) { bn = b2a; off = OB_2A; C = 128; c = j - 352; }
        else if (j < 608) { bn = b2b; off = OB_2B; C = 128; c = j - 480; }
        else              { bn = b2c; off = OB_2C; C = 128; c = j - 608; }
        float g = bn[c], b = bn[C + c], mu = bn[2 * C + c], v = bn[3 * C + c];
        float s = g * rsqrtf(v + EPSV);
        bnf[off + 2 * c] = s;
        bnf[off + 2 * c + 1] = b - s * mu;
    } else {
        int i2 = i - (WT_TOTAL + 736);            // float4 index in twt
        if (i2 >= WT_TOTAL / 2) return;
        int ff = 2 * i2;                           // float-offset equivalent
        const float* src; int off, cin, cout;
        if      (ff < O_W0B) { src = w0a; off = O_W0A; cin = 16;  cout = 32; }
        else if (ff < O_WD0) { src = w0b; off = O_W0B; cin = 32;  cout = 32; }
        else if (ff < O_W1A) { src = wd0; off = O_WD0; cin = 32;  cout = 32; }
        else if (ff < O_W1B) { src = w1a; off = O_W1A; cin = 32;  cout = 64; }
        else if (ff < O_WD1) { src = w1b; off = O_W1B; cin = 64;  cout = 64; }
        else if (ff < O_W2A) { src = wd1; off = O_WD1; cin = 64;  cout = 128; }
        else if (ff < O_W2B) { src = w2a; off = O_W2A; cin = 128; cout = 128; }
        else if (ff < O_W2C) { src = w2b; off = O_W2B; cin = 128; cout = 128; }
        else                 { src = w2c; off = O_W2C; cin = 128; cout = 128; }
        int r4 = i2 - off / 2;
        int lane = r4 & 31;
        int blk = r4 >> 5;
        int ntt = cout / 8, cs = cin / 8;
        int t = blk % ntt;
        int s = (blk / ntt) % cs;
        int kk = blk / (ntt * cs);
        int tg = lane & 3, gid = lane >> 2;
        int ci = s * 8 + tg;
        int co = t * 8 + gid;
        float w00 = src[(co * cin + ci) * 27 + kk];
        float w01 = src[(co * cin + ci + 4) * 27 + kk];
        uint32_t h0, l0, h1, l1;
        split_tf32(w00, h0, l0);
        split_tf32(w01, h1, l1);
        twt[i2] = make_float4(__uint_as_float(h0), __uint_as_float(h1),
                              __uint_as_float(l0), __uint_as_float(l1));
    }
}

// ----------------------------------------------------------------------------
// mask dtype probe (mode 0=u8 bool, 1=i32 bool, 2=f32, 3=bf16)
// ----------------------------------------------------------------------------
__global__ void probe_k(const unsigned char* __restrict__ b) {
    __shared__ int s_off1, s_big;
    if (threadIdx.x == 0) { s_off1 = 0; s_big = 0; }
    __syncthreads();
    int off1 = 0, big = 0;
    for (int i = threadIdx.x; i < 16384; i += blockDim.x) {
        unsigned char b0 = b[4 * i + 0], b1 = b[4 * i + 1];
        unsigned char b2 = b[4 * i + 2], b3 = b[4 * i + 3];
        if (b1) off1++;
        if (b0 > 1 || b1 > 1 || b2 > 1 || b3 > 1) big++;
    }
    atomicAdd(&s_off1, off1);
    atomicAdd(&s_big, big);
    __syncthreads();
    if (threadIdx.x == 0)
        g_mmode = (s_big == 0) ? ((s_off1 > 0) ? 0 : 1) : ((s_off1 > 0) ? 3 : 2);
}

__device__ __forceinline__ float mask_at(const unsigned char* b, int v, int mode) {
    if (mode == 0) return b[v] ? 1.f : 0.f;
    if (mode == 1) return ((const int*)b)[v] ? 1.f : 0.f;
    if (mode == 2) return (((const float*)b)[v] != 0.f) ? 1.f : 0.f;
    return (__bfloat162float(((const __nv_bfloat16*)b)[v]) != 0.f) ? 1.f : 0.f;
}

__global__ void premask_k(const float* __restrict__ x, const unsigned char* __restrict__ mb,
                          float* __restrict__ xm, float* __restrict__ m0) {
    int v = blockIdx.x * blockDim.x + threadIdx.x;
    if (v >= N0) return;
    int mode = g_mmode;
    float m = mask_at(mb, v, mode);
    m0[v] = m;
    int xx = v & 63, yy = (v >> 6) & 63, zz = v >> 12;
    int pidx = ((zz + 1) * PD0 + (yy + 1)) * PD0 + (xx + 1);
#pragma unroll
    for (int ci = 0; ci < 16; ci++) xm[ci * PD0_3 + pidx] = x[ci * N0 + v] * m;
}

template <int DIN>
__global__ void down_k(const float* __restrict__ mi, float* __restrict__ mo) {
    constexpr int DOUT = DIN / 2;
    int id = blockIdx.x * blockDim.x + threadIdx.x;
    if (id >= DOUT * DOUT * DOUT) return;
    int x = id % DOUT, y = (id / DOUT) % DOUT, z = id / (DOUT * DOUT);
    float m = 0.f;
#pragma unroll
    for (int dz = -1; dz <= 1; dz++) {
        int zz = 2 * z + dz; if ((unsigned)zz >= DIN) continue;
#pragma unroll
        for (int dy = -1; dy <= 1; dy++) {
            int yy = 2 * y + dy; if ((unsigned)yy >= DIN) continue;
#pragma unroll
            for (int dx = -1; dx <= 1; dx++) {
                int xx = 2 * x + dx; if ((unsigned)xx >= DIN) continue;
                m = fmaxf(m, mi[(zz * DIN + yy) * DIN + xx]);
            }
        }
    }
    mo[id] = m;
}

// ----------------------------------------------------------------------------
// tensor-core stride-1 conv v9: split accumulators, incremental tap pointers.
// grid = (COUT/NCH, DIN/YR, DIN); CTA 4 warps; warp = one 16-voxel m-tile.
// ----------------------------------------------------------------------------
template <int CIN, int COUT, int DIN, int NCH>
__global__ __launch_bounds__(128) void tconv_k(const float* __restrict__ in,
                                               const float4* __restrict__ wb,
                                               const float* __restrict__ bnf,
                                               const float* __restrict__ mask,
                                               float* __restrict__ out) {
    constexpr int PDI = DIN + 2;
    constexpr int PDI3 = PDI * PDI * PDI;
    constexpr int PDO = DIN + 2;
    constexpr int PDO3 = PDI3;
    constexpr int TPR = DIN / 16;     // m-tiles per row
    constexpr int YR = 64 / DIN;      // rows per CTA
    constexpr int NT = NCH / 8;       // n-tiles per warp
    constexpr int CS = CIN / 8;       // k8 steps per tap
    constexpr int NTT = COUT / 8;     // total n-tiles in twt layout

    const int warp = threadIdx.x >> 5, lane = threadIdx.x & 31;
    const int gid = lane >> 2, tg = lane & 3;
    const int nc = blockIdx.x;
    const int z = blockIdx.z;
    const int ym = blockIdx.y * YR + warp / TPR;
    const int xt = (warp % TPR) * 16;

    float chi[NT][4], cco[NT][4];
#pragma unroll
    for (int t = 0; t < NT; t++)
#pragma unroll
        for (int j = 0; j < 4; j++) { chi[t][j] = 0.f; cco[t][j] = 0.f; }

    const float* inb = in + tg * PDI3;
    const float4* bp = wb + nc * NT * 32 + lane;   // tap 0, s 0; advances linearly

#pragma unroll 1
    for (int dz = 0; dz < 3; dz++) {
#pragma unroll
        for (int dy = 0; dy < 3; dy++) {
            const float* rp = inb + ((z + dz) * PDI + (ym + dy)) * PDI + xt + gid;
#pragma unroll
            for (int dx = 0; dx < 3; dx++) {
                const float* ap = rp + dx;
#pragma unroll 2
                for (int s = 0; s < CS; s++) {
                    float a0f = __ldg(ap);
                    float a1f = __ldg(ap + 8);
                    float a2f = __ldg(ap + 4 * PDI3);
                    float a3f = __ldg(ap + 4 * PDI3 + 8);
                    uint32_t ah[4], al[4];
                    split_tf32(a0f, ah[0], al[0]);
                    split_tf32(a1f, ah[1], al[1]);
                    split_tf32(a2f, ah[2], al[2]);
                    split_tf32(a3f, ah[3], al[3]);
#pragma unroll
                    for (int t = 0; t < NT; t++) {
                        float4 bb = __ldg(bp + t * 32);
                        uint32_t bh0 = __float_as_uint(bb.x), bh1 = __float_as_uint(bb.y);
                        uint32_t bl0 = __float_as_uint(bb.z), bl1 = __float_as_uint(bb.w);
                        mma_tf32(chi[t], ah, bh0, bh1);   // hi*hi -> chain 1
                        mma_tf32(cco[t], ah, bl0, bl1);   // hi*lo -> chain 2
                        mma_tf32(cco[t], al, bh0, bh1);   // lo*hi -> chain 2
                    }
                    ap += 8 * PDI3;
                    bp += NTT * 32;
                }
            }
        }
    }

    // fused BN + ReLU + mask epilogue (padded output)
    int voxu = (z * DIN + ym) * DIN + xt;
    float mv0 = mask[voxu + gid];
    float mv1 = mask[voxu + gid + 8];
    int pv = ((z + 1) * PDO + (ym + 1)) * PDO + (xt + 1) + gid;
#pragma unroll
    for (int t = 0; t < NT; t++) {
        int c0 = nc * NCH + t * 8 + 2 * tg;
        float4 b4 = *reinterpret_cast<const float4*>(bnf + 2 * c0);
        float* o0 = out + c0 * PDO3 + pv;
        float* o1 = o0 + PDO3;
        float r0 = chi[t][0] + cco[t][0];
        float r1 = chi[t][1] + cco[t][1];
        float r2 = chi[t][2] + cco[t][2];
        float r3 = chi[t][3] + cco[t][3];
        o0[0] = fmaxf(fmaf(b4.x, r0, b4.y), 0.f) * mv0;
        o1[0] = fmaxf(fmaf(b4.z, r1, b4.w), 0.f) * mv0;
        o0[8] = fmaxf(fmaf(b4.x, r2, b4.y), 0.f) * mv1;
        o1[8] = fmaxf(fmaf(b4.z, r3, b4.w), 0.f) * mv1;
    }
}

// ----------------------------------------------------------------------------
// scalar conv (stride-2 layers) — unchanged v7
// ----------------------------------------------------------------------------
template <int CIN, int COUT, int STRIDE, int DIN, int SPLIT, int XT, int YT, int CH, bool FUSE>
__global__ __launch_bounds__(128, 4) void conv_k(const float* __restrict__ in,
                                                 const float* __restrict__ wt,
                                                 const float* __restrict__ bnf,
                                                 const float* __restrict__ mask,
                                                 float* __restrict__ out) {
    constexpr int DOUT = DIN / STRIDE;
    constexpr int PDI = DIN + 2;
    constexpr int PDI3 = PDI * PDI * PDI;
    constexpr int PDO = DOUT + 2;
    constexpr int PDO3 = PDO * PDO * PDO;
    constexpr int CHUNKS = COUT / CH;
    constexpr int CIB = CIN / SPLIT;
    constexpr int W = (XT - 1) * STRIDE + 3;
    constexpr int ROWS = (YT - 1) * STRIDE + 3;

    int tx = threadIdx.x, ty = threadIdx.y;
    int chunk = blockIdx.x % CHUNKS;
    int split = blockIdx.x / CHUNKS;
    int cb = chunk * CH;
    int y0 = (blockIdx.y * blockDim.y + ty) * YT;
    int z = blockIdx.z * blockDim.z + threadIdx.z;
    int x0 = XT * tx;

    float acc[YT * XT * CH];
#pragma unroll
    for (int i = 0; i < YT * XT * CH; i++) acc[i] = 0.f;

    const float* base = in + split * CIB * PDI3
                        + (z * STRIDE * PDI + y0 * STRIDE) * PDI + x0 * STRIDE;
    const float* wp = wt + (split * CIB * 27) * COUT + cb;

    for (int ci = 0; ci < CIB; ci++) {
#pragma unroll
        for (int dz = 0; dz < 3; dz++) {
            float v[ROWS][W];
#pragma unroll
            for (int r = 0; r < ROWS; r++) {
                const float* rp = base + (dz * PDI + r) * PDI;
                const float2* rp2 = reinterpret_cast<const float2*>(rp);
#pragma unroll
                for (int i = 0; i < W / 2; i++) {
                    float2 t = __ldg(rp2 + i);
                    v[r][2 * i] = t.x;
                    v[r][2 * i + 1] = t.y;
                }
                if (W & 1) v[r][W - 1] = __ldg(rp + W - 1);
            }
#pragma unroll
            for (int dy = 0; dy < 3; dy++)
#pragma unroll
                for (int dx = 0; dx < 3; dx++) {
                    const int k = (dz * 3 + dy) * 3 + dx;
                    const float4* w4 = reinterpret_cast<const float4*>(wp + k * COUT);
#pragma unroll
                    for (int j = 0; j < CH / 4; j++) {
                        float4 ww = __ldg(w4 + j);
#pragma unroll
                        for (int yt = 0; yt < YT; yt++)
#pragma unroll
                            for (int xt = 0; xt < XT; xt++) {
                                float a = v[yt * STRIDE + dy][xt * STRIDE + dx];
                                int o = (yt * XT + xt) * CH + 4 * j;
                                acc[o + 0] = fmaf(a, ww.x, acc[o + 0]);
                                acc[o + 1] = fmaf(a, ww.y, acc[o + 1]);
                                acc[o + 2] = fmaf(a, ww.z, acc[o + 2]);
                                acc[o + 3] = fmaf(a, ww.w, acc[o + 3]);
                            }
                    }
                }
        }
        base += PDI3;
        wp += 27 * COUT;
    }

    if (FUSE) {
#pragma unroll
        for (int yt = 0; yt < YT; yt++) {
            int voxu = (z * DOUT + y0 + yt) * DOUT + x0;
            float mm[XT];
#pragma unroll
            for (int xt = 0; xt < XT; xt++) mm[xt] = mask[voxu + xt];
            int pvox = ((z + 1) * PDO + (y0 + yt + 1)) * PDO + (x0 + 1);
#pragma unroll
            for (int i = 0; i < CH; i++) {
                int c = cb + i;
                float s = __ldg(bnf + 2 * c);
                float t = __ldg(bnf + 2 * c + 1);
#pragma unroll
                for (int xt = 0; xt < XT; xt++)
                    out[c * PDO3 + pvox + xt] =
                        fmaxf(fmaf(s, acc[(yt * XT + xt) * CH + i], t), 0.f) * mm[xt];
            }
        }
    } else {
        constexpr int N = DOUT * DOUT * DOUT;
#pragma unroll
        for (int yt = 0; yt < YT; yt++) {
            int vox = (z * DOUT + y0 + yt) * DOUT + x0;
#pragma unroll
            for (int i = 0; i < CH; i++) {
                int c = cb + i;
#pragma unroll
                for (int xt = 0; xt < XT; xt++)
                    out[(split * COUT + c) * N + vox + xt] = acc[(yt * XT + xt) * CH + i];
            }
        }
    }
}

// epilogue for split convs
template <int COUT, int DOUT, int SPLIT>
__global__ void epi_k(const float* __restrict__ part, const float* __restrict__ bnf,
                      const float* __restrict__ mask, float* __restrict__ out) {
    constexpr int N = DOUT * DOUT * DOUT;
    constexpr int PDO = DOUT + 2;
    constexpr int PDO3 = PDO * PDO * PDO;
    int id = blockIdx.x * blockDim.x + threadIdx.x;
    if (id >= COUT * N) return;
    int vox = id % N, c = id / N;
    float a = 0.f;
#pragma unroll
    for (int s = 0; s < SPLIT; s++) a += part[(s * COUT + c) * N + vox];
    float sc = __ldg(bnf + 2 * c), t = __ldg(bnf + 2 * c + 1);
    int x = vox % DOUT, y = (vox / DOUT) % DOUT, z = vox / (DOUT * DOUT);
    out[c * PDO3 + ((z + 1) * PDO + (y + 1)) * PDO + (x + 1)] =
        fmaxf(fmaf(sc, a, t), 0.f) * mask[vox];
}

// ----------------------------------------------------------------------------
// triplane means + sampler
// ----------------------------------------------------------------------------
__global__ void planes_k(const float* __restrict__ f, float* __restrict__ pl) {
    int id = blockIdx.x * blockDim.x + threadIdx.x;
    if (id >= 3 * 16 * 16 * 128) return;
    int c = id & 127;
    int rem = id >> 7;
    int b = rem & 15;
    int a = (rem >> 4) & 15;
    int t = rem >> 8;
    const float* fc = f + c * PD2_3;
    float s = 0.f;
    if (t == 0) {
#pragma unroll
        for (int z = 0; z < 16; z++) s += fc[((z + 1) * PD2 + (a + 1)) * PD2 + (b + 1)];
    } else if (t == 1) {
#pragma unroll
        for (int xx = 0; xx < 16; xx++) s += fc[((a + 1) * PD2 + (b + 1)) * PD2 + (xx + 1)];
    } else {
#pragma unroll
        for (int yy = 0; yy < 16; yy++) s += fc[((a + 1) * PD2 + (yy + 1)) * PD2 + (b + 1)];
    }
    pl[t * (16 * 16 * 128) + (a * 16 + b) * 128 + c] = s * (1.f / 16.f);
}

__device__ __forceinline__ float samp2d(const float* __restrict__ img, float gx, float gy, int c) {
    float ix = (gx + 1.f) * 0.5f * 15.f;
    float iy = (gy + 1.f) * 0.5f * 15.f;
    float x0f = floorf(ix), y0f = floorf(iy);
    int x0 = (int)x0f, y0 = (int)y0f;
    float wx = ix - x0f, wy = iy - y0f;
    float r = 0.f;
#pragma unroll
    for (int dy = 0; dy < 2; dy++)
#pragma unroll
        for (int dx = 0; dx < 2; dx++) {
            int xx = x0 + dx, yy = y0 + dy;
            float w = (dy ? wy : 1.f - wy) * (dx ? wx : 1.f - wx);
            bool ok = ((unsigned)xx < 16u) && ((unsigned)yy < 16u);
            int xc = min(max(xx, 0), 15), yc = min(max(yy, 0), 15);
            float v = __ldg(img + (yc * 16 + xc) * 128 + c);
            r += v * (ok ? w : 0.f);
        }
    return r;
}

__global__ void sample_k(const float* __restrict__ coords, const float* __restrict__ planes,
                         float* __restrict__ out) {
    constexpr int PTS = 16;
    int c = threadIdx.x;  // 128
    int p0 = blockIdx.x * PTS;
#pragma unroll 1
    for (int i = 0; i < PTS; i++) {
        int p = p0 + i;
        float c0 = __ldg(coords + 3 * p + 0);
        float c1 = __ldg(coords + 3 * p + 1);
        float c2 = __ldg(coords + 3 * p + 2);
        float s = samp2d(planes + 0 * (16 * 16 * 128), c0, c1, c)
                + samp2d(planes + 1 * (16 * 16 * 128), c1, c2, c)
                + samp2d(planes + 2 * (16 * 16 * 128), c0, c2, c);
        out[(size_t)p * 128 + c] = s;
    }
}

// ----------------------------------------------------------------------------
// launch — launch #4 is tconv0a (ncu target)
// ----------------------------------------------------------------------------
extern "C" void kernel_launch(void* const* d_in, const int* in_sizes, int n_in,
                              void* d_out, int out_size) {
    const float* x = (const float*)d_in[0];
    const unsigned char* mask = (const unsigned char*)d_in[1];
    const float* coords = (const float*)d_in[2];
    const float* w0a = (const float*)d_in[3];  const float* bn0a = (const float*)d_in[4];
    const float* w0b = (const float*)d_in[5];  const float* bn0b = (const float*)d_in[6];
    const float* wd0 = (const float*)d_in[7];  const float* bnd0 = (const float*)d_in[8];
    const float* w1a = (const float*)d_in[9];  const float* bn1a = (const float*)d_in[10];
    const float* w1b = (const float*)d_in[11]; const float* bn1b = (const float*)d_in[12];
    const float* wd1 = (const float*)d_in[13]; const float* bnd1 = (const float*)d_in[14];
    const float* w2a = (const float*)d_in[15]; const float* bn2a = (const float*)d_in[16];
    const float* w2b = (const float*)d_in[17]; const float* bn2b = (const float*)d_in[18];
    const float* w2c = (const float*)d_in[19]; const float* bn2c = (const float*)d_in[20];

    float *xm, *A0, *B0, *A1, *B1, *A2, *B2, *part, *m0, *m1, *m2, *wt, *bnf, *pl;
    float4* twt;
    cudaGetSymbolAddress((void**)&xm, g_xm);
    cudaGetSymbolAddress((void**)&A0, g_A0);
    cudaGetSymbolAddress((void**)&B0, g_B0);
    cudaGetSymbolAddress((void**)&A1, g_A1);
    cudaGetSymbolAddress((void**)&B1, g_B1);
    cudaGetSymbolAddress((void**)&A2, g_A2);
    cudaGetSymbolAddress((void**)&B2, g_B2);
    cudaGetSymbolAddress((void**)&part, g_part);
    cudaGetSymbolAddress((void**)&m0, g_m0);
    cudaGetSymbolAddress((void**)&m1, g_m1);
    cudaGetSymbolAddress((void**)&m2, g_m2);
    cudaGetSymbolAddress((void**)&wt, g_wt);
    cudaGetSymbolAddress((void**)&twt, g_twt);
    cudaGetSymbolAddress((void**)&bnf, g_bnf);
    cudaGetSymbolAddress((void**)&pl, g_planes);

    // 1-3: probe, merged prep (wt + bn + twt), premask
    probe_k<<<1, 256>>>(mask);
    int prtot = WT_TOTAL + 736 + WT_TOTAL / 2;
    prep_k<<<(prtot + 255) / 256, 256>>>(w0a, w0b, wd0, w1a, w1b, wd1, w2a, w2b, w2c,
                                         bn0a, bn0b, bnd0, bn1a, bn1b, bnd1, bn2a, bn2b, bn2c,
                                         wt, bnf, twt);
    premask_k<<<(N0 + 255) / 256, 256>>>(x, mask, xm, m0);

    // 4-6: tensor-core conv0a (ncu target), conv0b, scalar convd0
    tconv_k<16, 32, 64, 32><<<dim3(1, 64, 64), 128>>>(xm, twt + O_W0A / 2, bnf + OB_0A, m0, A0);
    tconv_k<32, 32, 64, 32><<<dim3(1, 64, 64), 128>>>(A0, twt + O_W0B / 2, bnf + OB_0B, m0, B0);
    conv_k<32, 32, 2, 64, 2, 2, 1, 16, false><<<dim3(4, 4, 32), dim3(16, 8)>>>(B0, wt + O_WD0, nullptr, nullptr, part);

    // 7-9: mask downsamples + epi_d0
    down_k<64><<<(N1 + 255) / 256, 256>>>(m0, m1);
    epi_k<32, 32, 2><<<(32 * N1 + 255) / 256, 256>>>(part, bnf + OB_D0, m1, A1);
    down_k<32><<<(N2 + 255) / 256, 256>>>(m1, m2);

    // 10-13: stage 1 @32^3 (tensor, NCH=32 -> 1024 CTAs) + downsample 1 (scalar)
    tconv_k<32, 64, 32, 32><<<dim3(2, 16, 32), 128>>>(A1, twt + O_W1A / 2, bnf + OB_1A, m1, B1);
    tconv_k<64, 64, 32, 32><<<dim3(2, 16, 32), 128>>>(B1, twt + O_W1B / 2, bnf + OB_1B, m1, A1);
    conv_k<64, 128, 2, 32, 4, 2, 1, 16, false><<<dim3(32, 1, 16), dim3(8, 16)>>>(A1, wt + O_WD1, nullptr, nullptr, part);
    epi_k<128, 16, 4><<<(128 * N2 + 255) / 256, 256>>>(part, bnf + OB_D1, m2, A2);

    // 14-16: stage 2 @16^3 (tensor, NCH=16 -> 512 CTAs each)
    tconv_k<128, 128, 16, 16><<<dim3(8, 4, 16), 128>>>(A2, twt + O_W2A / 2, bnf + OB_2A, m2, B2);
    tconv_k<128, 128, 16, 16><<<dim3(8, 4, 16), 128>>>(B2, twt + O_W2B / 2, bnf + OB_2B, m2, A2);
    tconv_k<128, 128, 16, 16><<<dim3(8, 4, 16), 128>>>(A2, twt + O_W2C / 2, bnf + OB_2C, m2, B2);

    // 17-18: triplane + sample
    planes_k<<<(3 * 16 * 16 * 128 + 255) / 256, 256>>>(B2, pl);
    sample_k<<<NPTS / 16, 128>>>(coords, pl, (float*)d_out);
}

// round 15
// speedup vs baseline: 1.4532x; 1.1702x over previous
#include <cuda_runtime.h>
#include <cuda_bf16.h>
#include <cstdint>

// ============================================================================
// SparseConvNet_Triplane v10: measured-winner hybrid.
// tconv (3xTF32 mma) ONLY for conv0a/conv0b @64^3 (where it beat scalar);
// scalar v7 conv for stage 1, stage 2, and stride-2 layers.
// ============================================================================

#define EPSV 1e-3f

static constexpr int N0 = 64 * 64 * 64;
static constexpr int N1 = 32 * 32 * 32;
static constexpr int N2 = 16 * 16 * 16;
static constexpr int NPTS = 65536;

static constexpr int PD0 = 66, PD0_3 = PD0 * PD0 * PD0;
static constexpr int PD1 = 34, PD1_3 = PD1 * PD1 * PD1;
static constexpr int PD2 = 18, PD2_3 = PD2 * PD2 * PD2;

// weight segments (float counts), scalar layout [ci][k][co]
static constexpr int O_W0A = 0;
static constexpr int O_W0B = O_W0A + 16 * 32 * 27;
static constexpr int O_WD0 = O_W0B + 32 * 32 * 27;
static constexpr int O_W1A = O_WD0 + 32 * 32 * 27;
static constexpr int O_W1B = O_W1A + 32 * 64 * 27;
static constexpr int O_WD1 = O_W1B + 64 * 64 * 27;
static constexpr int O_W2A = O_WD1 + 64 * 128 * 27;
static constexpr int O_W2B = O_W2A + 128 * 128 * 27;
static constexpr int O_W2C = O_W2B + 128 * 128 * 27;
static constexpr int WT_TOTAL = O_W2C + 128 * 128 * 27;

// fused BN scale/shift segments
static constexpr int OB_0A = 0;
static constexpr int OB_0B = OB_0A + 2 * 32;
static constexpr int OB_D0 = OB_0B + 2 * 32;
static constexpr int OB_1A = OB_D0 + 2 * 32;
static constexpr int OB_1B = OB_1A + 2 * 64;
static constexpr int OB_D1 = OB_1B + 2 * 64;
static constexpr int OB_2A = OB_D1 + 2 * 128;
static constexpr int OB_2B = OB_2A + 2 * 128;
static constexpr int OB_2C = OB_2B + 2 * 128;

// static scratch; halos of padded buffers never written -> stay 0
__device__ __align__(16) float g_xm[16 * PD0_3];
__device__ __align__(16) float g_A0[32 * PD0_3];
__device__ __align__(16) float g_B0[32 * PD0_3];
__device__ __align__(16) float g_A1[64 * PD1_3];
__device__ __align__(16) float g_B1[64 * PD1_3];
__device__ __align__(16) float g_A2[128 * PD2_3];
__device__ __align__(16) float g_B2[128 * PD2_3];
__device__ __align__(16) float g_part[2097152];
__device__ float g_m0[N0];
__device__ float g_m1[N1];
__device__ float g_m2[N2];
__device__ __align__(16) float g_wt[WT_TOTAL];
__device__ __align__(16) float4 g_twt[(O_WD0) / 2];    // tf32 tiles only for w0a+w0b
__device__ __align__(16) float g_bnf[OB_2C + 2 * 128];
__device__ __align__(16) float g_planes[3 * 16 * 16 * 128];
__device__ int g_mmode;

// ----------------------------------------------------------------------------
// tf32 helpers
// ----------------------------------------------------------------------------
__device__ __forceinline__ uint32_t tf32_of(float a) {
    uint32_t r;
    asm("cvt.rna.tf32.f32 %0, %1;" : "=r"(r) : "f"(a));
    return r;
}
__device__ __forceinline__ void split_tf32(float a, uint32_t& hi, uint32_t& lo) {
    hi = tf32_of(a);
    lo = tf32_of(a - __uint_as_float(hi));
}
__device__ __forceinline__ void mma_tf32(float* c, const uint32_t* a, uint32_t b0, uint32_t b1) {
    asm("mma.sync.aligned.m16n8k8.row.col.f32.tf32.tf32.f32 "
        "{%0,%1,%2,%3}, {%4,%5,%6,%7}, {%8,%9}, {%0,%1,%2,%3};"
        : "+f"(c[0]), "+f"(c[1]), "+f"(c[2]), "+f"(c[3])
        : "r"(a[0]), "r"(a[1]), "r"(a[2]), "r"(a[3]), "r"(b0), "r"(b1));
}

// ----------------------------------------------------------------------------
// merged prep: scalar wt transpose + BN fusion + tf32 hi/lo tiles (w0a,w0b only)
// ----------------------------------------------------------------------------
__global__ void prep_k(const float* __restrict__ w0a, const float* __restrict__ w0b,
                       const float* __restrict__ wd0, const float* __restrict__ w1a,
                       const float* __restrict__ w1b, const float* __restrict__ wd1,
                       const float* __restrict__ w2a, const float* __restrict__ w2b,
                       const float* __restrict__ w2c,
                       const float* __restrict__ b0a, const float* __restrict__ b0b,
                       const float* __restrict__ bd0, const float* __restrict__ b1a,
                       const float* __restrict__ b1b, const float* __restrict__ bd1,
                       const float* __restrict__ b2a, const float* __restrict__ b2b,
                       const float* __restrict__ b2c,
                       float* __restrict__ wt, float* __restrict__ bnf,
                       float4* __restrict__ twt) {
    int i = blockIdx.x * blockDim.x + threadIdx.x;
    if (i < WT_TOTAL) {
        const float* src; int off, cin, cout;
        if      (i < O_W0B) { src = w0a; off = O_W0A; cin = 16;  cout = 32; }
        else if (i < O_WD0) { src = w0b; off = O_W0B; cin = 32;  cout = 32; }
        else if (i < O_W1A) { src = wd0; off = O_WD0; cin = 32;  cout = 32; }
        else if (i < O_W1B) { src = w1a; off = O_W1A; cin = 32;  cout = 64; }
        else if (i < O_WD1) { src = w1b; off = O_W1B; cin = 64;  cout = 64; }
        else if (i < O_W2A) { src = wd1; off = O_WD1; cin = 64;  cout = 128; }
        else if (i < O_W2B) { src = w2a; off = O_W2A; cin = 128; cout = 128; }
        else if (i < O_W2C) { src = w2b; off = O_W2B; cin = 128; cout = 128; }
        else                { src = w2c; off = O_W2C; cin = 128; cout = 128; }
        int r = i - off;
        int co = r % cout;
        int k  = (r / cout) % 27;
        int ci = r / (cout * 27);
        wt[i] = src[(co * cin + ci) * 27 + k];
    } else if (i < WT_TOTAL + 736) {
        int j = i - WT_TOTAL;
        const float* bn; int off, C, c;
        if      (j < 32)  { bn = b0a; off = OB_0A; C = 32;  c = j; }
        else if (j < 64)  { bn = b0b; off = OB_0B; C = 32;  c = j - 32; }
        else if (j < 96)  { bn = bd0; off = OB_D0; C = 32;  c = j - 64; }
        else if (j < 160) { bn = b1a; off = OB_1A; C = 64;  c = j - 96; }
        else if (j < 224) { bn = b1b; off = OB_1B; C = 64;  c = j - 160; }
        else if (j < 352) { bn = bd1; off = OB_D1; C = 128; c = j - 224; }
        else if (j < 480) { bn = b2a; off = OB_2A; C = 128; c = j - 352; }
        else if (j < 608) { bn = b2b; off = OB_2B; C = 128; c = j - 480; }
        else              { bn = b2c; off = OB_2C; C = 128; c = j - 608; }
        float g = bn[c], b = bn[C + c], mu = bn[2 * C + c], v = bn[3 * C + c];
        float s = g * rsqrtf(v + EPSV);
        bnf[off + 2 * c] = s;
        bnf[off + 2 * c + 1] = b - s * mu;
    } else {
        int i2 = i - (WT_TOTAL + 736);            // float4 index in twt
        if (i2 >= O_WD0 / 2) return;
        int ff = 2 * i2;
        const float* src; int off, cin, cout;
        if (ff < O_W0B) { src = w0a; off = O_W0A; cin = 16; cout = 32; }
        else            { src = w0b; off = O_W0B; cin = 32; cout = 32; }
        int r4 = i2 - off / 2;
        int lane = r4 & 31;
        int blk = r4 >> 5;
        int ntt = cout / 8, cs = cin / 8;
        int t = blk % ntt;
        int s = (blk / ntt) % cs;
        int kk = blk / (ntt * cs);
        int tg = lane & 3, gid = lane >> 2;
        int ci = s * 8 + tg;
        int co = t * 8 + gid;
        float w00 = src[(co * cin + ci) * 27 + kk];
        float w01 = src[(co * cin + ci + 4) * 27 + kk];
        uint32_t h0, l0, h1, l1;
        split_tf32(w00, h0, l0);
        split_tf32(w01, h1, l1);
        twt[i2] = make_float4(__uint_as_float(h0), __uint_as_float(h1),
                              __uint_as_float(l0), __uint_as_float(l1));
    }
}

// ----------------------------------------------------------------------------
// mask dtype probe (mode 0=u8 bool, 1=i32 bool, 2=f32, 3=bf16)
// ----------------------------------------------------------------------------
__global__ void probe_k(const unsigned char* __restrict__ b) {
    __shared__ int s_off1, s_big;
    if (threadIdx.x == 0) { s_off1 = 0; s_big = 0; }
    __syncthreads();
    int off1 = 0, big = 0;
    for (int i = threadIdx.x; i < 16384; i += blockDim.x) {
        unsigned char b0 = b[4 * i + 0], b1 = b[4 * i + 1];
        unsigned char b2 = b[4 * i + 2], b3 = b[4 * i + 3];
        if (b1) off1++;
        if (b0 > 1 || b1 > 1 || b2 > 1 || b3 > 1) big++;
    }
    atomicAdd(&s_off1, off1);
    atomicAdd(&s_big, big);
    __syncthreads();
    if (threadIdx.x == 0)
        g_mmode = (s_big == 0) ? ((s_off1 > 0) ? 0 : 1) : ((s_off1 > 0) ? 3 : 2);
}

__device__ __forceinline__ float mask_at(const unsigned char* b, int v, int mode) {
    if (mode == 0) return b[v] ? 1.f : 0.f;
    if (mode == 1) return ((const int*)b)[v] ? 1.f : 0.f;
    if (mode == 2) return (((const float*)b)[v] != 0.f) ? 1.f : 0.f;
    return (__bfloat162float(((const __nv_bfloat16*)b)[v]) != 0.f) ? 1.f : 0.f;
}

__global__ void premask_k(const float* __restrict__ x, const unsigned char* __restrict__ mb,
                          float* __restrict__ xm, float* __restrict__ m0) {
    int v = blockIdx.x * blockDim.x + threadIdx.x;
    if (v >= N0) return;
    int mode = g_mmode;
    float m = mask_at(mb, v, mode);
    m0[v] = m;
    int xx = v & 63, yy = (v >> 6) & 63, zz = v >> 12;
    int pidx = ((zz + 1) * PD0 + (yy + 1)) * PD0 + (xx + 1);
#pragma unroll
    for (int ci = 0; ci < 16; ci++) xm[ci * PD0_3 + pidx] = x[ci * N0 + v] * m;
}

template <int DIN>
__global__ void down_k(const float* __restrict__ mi, float* __restrict__ mo) {
    constexpr int DOUT = DIN / 2;
    int id = blockIdx.x * blockDim.x + threadIdx.x;
    if (id >= DOUT * DOUT * DOUT) return;
    int x = id % DOUT, y = (id / DOUT) % DOUT, z = id / (DOUT * DOUT);
    float m = 0.f;
#pragma unroll
    for (int dz = -1; dz <= 1; dz++) {
        int zz = 2 * z + dz; if ((unsigned)zz >= DIN) continue;
#pragma unroll
        for (int dy = -1; dy <= 1; dy++) {
            int yy = 2 * y + dy; if ((unsigned)yy >= DIN) continue;
#pragma unroll
            for (int dx = -1; dx <= 1; dx++) {
                int xx = 2 * x + dx; if ((unsigned)xx >= DIN) continue;
                m = fmaxf(m, mi[(zz * DIN + yy) * DIN + xx]);
            }
        }
    }
    mo[id] = m;
}

// ----------------------------------------------------------------------------
// tensor-core stride-1 conv (v9): split accumulators, incremental tap pointers.
// Used ONLY for the 64^3 layers where it measured faster than scalar.
// ----------------------------------------------------------------------------
template <int CIN, int COUT, int DIN, int NCH>
__global__ __launch_bounds__(128) void tconv_k(const float* __restrict__ in,
                                               const float4* __restrict__ wb,
                                               const float* __restrict__ bnf,
                                               const float* __restrict__ mask,
                                               float* __restrict__ out) {
    constexpr int PDI = DIN + 2;
    constexpr int PDI3 = PDI * PDI * PDI;
    constexpr int PDO = DIN + 2;
    constexpr int PDO3 = PDI3;
    constexpr int TPR = DIN / 16;
    constexpr int YR = 64 / DIN;
    constexpr int NT = NCH / 8;
    constexpr int CS = CIN / 8;
    constexpr int NTT = COUT / 8;

    const int warp = threadIdx.x >> 5, lane = threadIdx.x & 31;
    const int gid = lane >> 2, tg = lane & 3;
    const int nc = blockIdx.x;
    const int z = blockIdx.z;
    const int ym = blockIdx.y * YR + warp / TPR;
    const int xt = (warp % TPR) * 16;

    float chi[NT][4], cco[NT][4];
#pragma unroll
    for (int t = 0; t < NT; t++)
#pragma unroll
        for (int j = 0; j < 4; j++) { chi[t][j] = 0.f; cco[t][j] = 0.f; }

    const float* inb = in + tg * PDI3;
    const float4* bp = wb + nc * NT * 32 + lane;

#pragma unroll 1
    for (int dz = 0; dz < 3; dz++) {
#pragma unroll
        for (int dy = 0; dy < 3; dy++) {
            const float* rp = inb + ((z + dz) * PDI + (ym + dy)) * PDI + xt + gid;
#pragma unroll
            for (int dx = 0; dx < 3; dx++) {
                const float* ap = rp + dx;
#pragma unroll 2
                for (int s = 0; s < CS; s++) {
                    float a0f = __ldg(ap);
                    float a1f = __ldg(ap + 8);
                    float a2f = __ldg(ap + 4 * PDI3);
                    float a3f = __ldg(ap + 4 * PDI3 + 8);
                    uint32_t ah[4], al[4];
                    split_tf32(a0f, ah[0], al[0]);
                    split_tf32(a1f, ah[1], al[1]);
                    split_tf32(a2f, ah[2], al[2]);
                    split_tf32(a3f, ah[3], al[3]);
#pragma unroll
                    for (int t = 0; t < NT; t++) {
                        float4 bb = __ldg(bp + t * 32);
                        uint32_t bh0 = __float_as_uint(bb.x), bh1 = __float_as_uint(bb.y);
                        uint32_t bl0 = __float_as_uint(bb.z), bl1 = __float_as_uint(bb.w);
                        mma_tf32(chi[t], ah, bh0, bh1);
                        mma_tf32(cco[t], ah, bl0, bl1);
                        mma_tf32(cco[t], al, bh0, bh1);
                    }
                    ap += 8 * PDI3;
                    bp += NTT * 32;
                }
            }
        }
    }

    int voxu = (z * DIN + ym) * DIN + xt;
    float mv0 = mask[voxu + gid];
    float mv1 = mask[voxu + gid + 8];
    int pv = ((z + 1) * PDO + (ym + 1)) * PDO + (xt + 1) + gid;
#pragma unroll
    for (int t = 0; t < NT; t++) {
        int c0 = nc * NCH + t * 8 + 2 * tg;
        float4 b4 = *reinterpret_cast<const float4*>(bnf + 2 * c0);
        float* o0 = out + c0 * PDO3 + pv;
        float* o1 = o0 + PDO3;
        float r0 = chi[t][0] + cco[t][0];
        float r1 = chi[t][1] + cco[t][1];
        float r2 = chi[t][2] + cco[t][2];
        float r3 = chi[t][3] + cco[t][3];
        o0[0] = fmaxf(fmaf(b4.x, r0, b4.y), 0.f) * mv0;
        o1[0] = fmaxf(fmaf(b4.z, r1, b4.w), 0.f) * mv0;
        o0[8] = fmaxf(fmaf(b4.x, r2, b4.y), 0.f) * mv1;
        o1[8] = fmaxf(fmaf(b4.z, r3, b4.w), 0.f) * mv1;
    }
}

// ----------------------------------------------------------------------------
// scalar conv (v7) — stage 1, stage 2, stride-2 layers
// ----------------------------------------------------------------------------
template <int CIN, int COUT, int STRIDE, int DIN, int SPLIT, int XT, int YT, int CH, bool FUSE>
__global__ __launch_bounds__(128, 4) void conv_k(const float* __restrict__ in,
                                                 const float* __restrict__ wt,
                                                 const float* __restrict__ bnf,
                                                 const float* __restrict__ mask,
                                                 float* __restrict__ out) {
    constexpr int DOUT = DIN / STRIDE;
    constexpr int PDI = DIN + 2;
    constexpr int PDI3 = PDI * PDI * PDI;
    constexpr int PDO = DOUT + 2;
    constexpr int PDO3 = PDO * PDO * PDO;
    constexpr int CHUNKS = COUT / CH;
    constexpr int CIB = CIN / SPLIT;
    constexpr int W = (XT - 1) * STRIDE + 3;
    constexpr int ROWS = (YT - 1) * STRIDE + 3;

    int tx = threadIdx.x, ty = threadIdx.y;
    int chunk = blockIdx.x % CHUNKS;
    int split = blockIdx.x / CHUNKS;
    int cb = chunk * CH;
    int y0 = (blockIdx.y * blockDim.y + ty) * YT;
    int z = blockIdx.z * blockDim.z + threadIdx.z;
    int x0 = XT * tx;

    float acc[YT * XT * CH];
#pragma unroll
    for (int i = 0; i < YT * XT * CH; i++) acc[i] = 0.f;

    const float* base = in + split * CIB * PDI3
                        + (z * STRIDE * PDI + y0 * STRIDE) * PDI + x0 * STRIDE;
    const float* wp = wt + (split * CIB * 27) * COUT + cb;

    for (int ci = 0; ci < CIB; ci++) {
#pragma unroll
        for (int dz = 0; dz < 3; dz++) {
            float v[ROWS][W];
#pragma unroll
            for (int r = 0; r < ROWS; r++) {
                const float* rp = base + (dz * PDI + r) * PDI;
                const float2* rp2 = reinterpret_cast<const float2*>(rp);
#pragma unroll
                for (int i = 0; i < W / 2; i++) {
                    float2 t = __ldg(rp2 + i);
                    v[r][2 * i] = t.x;
                    v[r][2 * i + 1] = t.y;
                }
                if (W & 1) v[r][W - 1] = __ldg(rp + W - 1);
            }
#pragma unroll
            for (int dy = 0; dy < 3; dy++)
#pragma unroll
                for (int dx = 0; dx < 3; dx++) {
                    const int k = (dz * 3 + dy) * 3 + dx;
                    const float4* w4 = reinterpret_cast<const float4*>(wp + k * COUT);
#pragma unroll
                    for (int j = 0; j < CH / 4; j++) {
                        float4 ww = __ldg(w4 + j);
#pragma unroll
                        for (int yt = 0; yt < YT; yt++)
#pragma unroll
                            for (int xt = 0; xt < XT; xt++) {
                                float a = v[yt * STRIDE + dy][xt * STRIDE + dx];
                                int o = (yt * XT + xt) * CH + 4 * j;
                                acc[o + 0] = fmaf(a, ww.x, acc[o + 0]);
                                acc[o + 1] = fmaf(a, ww.y, acc[o + 1]);
                                acc[o + 2] = fmaf(a, ww.z, acc[o + 2]);
                                acc[o + 3] = fmaf(a, ww.w, acc[o + 3]);
                            }
                    }
                }
        }
        base += PDI3;
        wp += 27 * COUT;
    }

    if (FUSE) {
#pragma unroll
        for (int yt = 0; yt < YT; yt++) {
            int voxu = (z * DOUT + y0 + yt) * DOUT + x0;
            float mm[XT];
#pragma unroll
            for (int xt = 0; xt < XT; xt++) mm[xt] = mask[voxu + xt];
            int pvox = ((z + 1) * PDO + (y0 + yt + 1)) * PDO + (x0 + 1);
#pragma unroll
            for (int i = 0; i < CH; i++) {
                int c = cb + i;
                float s = __ldg(bnf + 2 * c);
                float t = __ldg(bnf + 2 * c + 1);
#pragma unroll
                for (int xt = 0; xt < XT; xt++)
                    out[c * PDO3 + pvox + xt] =
                        fmaxf(fmaf(s, acc[(yt * XT + xt) * CH + i], t), 0.f) * mm[xt];
            }
        }
    } else {
        constexpr int N = DOUT * DOUT * DOUT;
#pragma unroll
        for (int yt = 0; yt < YT; yt++) {
            int vox = (z * DOUT + y0 + yt) * DOUT + x0;
#pragma unroll
            for (int i = 0; i < CH; i++) {
                int c = cb + i;
#pragma unroll
                for (int xt = 0; xt < XT; xt++)
                    out[(split * COUT + c) * N + vox + xt] = acc[(yt * XT + xt) * CH + i];
            }
        }
    }
}

// epilogue for split convs
template <int COUT, int DOUT, int SPLIT>
__global__ void epi_k(const float* __restrict__ part, const float* __restrict__ bnf,
                      const float* __restrict__ mask, float* __restrict__ out) {
    constexpr int N = DOUT * DOUT * DOUT;
    constexpr int PDO = DOUT + 2;
    constexpr int PDO3 = PDO * PDO * PDO;
    int id = blockIdx.x * blockDim.x + threadIdx.x;
    if (id >= COUT * N) return;
    int vox = id % N, c = id / N;
    float a = 0.f;
#pragma unroll
    for (int s = 0; s < SPLIT; s++) a += part[(s * COUT + c) * N + vox];
    float sc = __ldg(bnf + 2 * c), t = __ldg(bnf + 2 * c + 1);
    int x = vox % DOUT, y = (vox / DOUT) % DOUT, z = vox / (DOUT * DOUT);
    out[c * PDO3 + ((z + 1) * PDO + (y + 1)) * PDO + (x + 1)] =
        fmaxf(fmaf(sc, a, t), 0.f) * mask[vox];
}

// ----------------------------------------------------------------------------
// triplane means + sampler
// ----------------------------------------------------------------------------
__global__ void planes_k(const float* __restrict__ f, float* __restrict__ pl) {
    int id = blockIdx.x * blockDim.x + threadIdx.x;
    if (id >= 3 * 16 * 16 * 128) return;
    int c = id & 127;
    int rem = id >> 7;
    int b = rem & 15;
    int a = (rem >> 4) & 15;
    int t = rem >> 8;
    const float* fc = f + c * PD2_3;
    float s = 0.f;
    if (t == 0) {
#pragma unroll
        for (int z = 0; z < 16; z++) s += fc[((z + 1) * PD2 + (a + 1)) * PD2 + (b + 1)];
    } else if (t == 1) {
#pragma unroll
        for (int xx = 0; xx < 16; xx++) s += fc[((a + 1) * PD2 + (b + 1)) * PD2 + (xx + 1)];
    } else {
#pragma unroll
        for (int yy = 0; yy < 16; yy++) s += fc[((a + 1) * PD2 + (yy + 1)) * PD2 + (b + 1)];
    }
    pl[t * (16 * 16 * 128) + (a * 16 + b) * 128 + c] = s * (1.f / 16.f);
}

__device__ __forceinline__ float samp2d(const float* __restrict__ img, float gx, float gy, int c) {
    float ix = (gx + 1.f) * 0.5f * 15.f;
    float iy = (gy + 1.f) * 0.5f * 15.f;
    float x0f = floorf(ix), y0f = floorf(iy);
    int x0 = (int)x0f, y0 = (int)y0f;
    float wx = ix - x0f, wy = iy - y0f;
    float r = 0.f;
#pragma unroll
    for (int dy = 0; dy < 2; dy++)
#pragma unroll
        for (int dx = 0; dx < 2; dx++) {
            int xx = x0 + dx, yy = y0 + dy;
            float w = (dy ? wy : 1.f - wy) * (dx ? wx : 1.f - wx);
            bool ok = ((unsigned)xx < 16u) && ((unsigned)yy < 16u);
            int xc = min(max(xx, 0), 15), yc = min(max(yy, 0), 15);
            float v = __ldg(img + (yc * 16 + xc) * 128 + c);
            r += v * (ok ? w : 0.f);
        }
    return r;
}

__global__ void sample_k(const float* __restrict__ coords, const float* __restrict__ planes,
                         float* __restrict__ out) {
    constexpr int PTS = 16;
    int c = threadIdx.x;  // 128
    int p0 = blockIdx.x * PTS;
#pragma unroll 1
    for (int i = 0; i < PTS; i++) {
        int p = p0 + i;
        float c0 = __ldg(coords + 3 * p + 0);
        float c1 = __ldg(coords + 3 * p + 1);
        float c2 = __ldg(coords + 3 * p + 2);
        float s = samp2d(planes + 0 * (16 * 16 * 128), c0, c1, c)
                + samp2d(planes + 1 * (16 * 16 * 128), c1, c2, c)
                + samp2d(planes + 2 * (16 * 16 * 128), c0, c2, c);
        out[(size_t)p * 128 + c] = s;
    }
}

// ----------------------------------------------------------------------------
// launch — launch #4 is tconv0a (ncu target)
// ----------------------------------------------------------------------------
extern "C" void kernel_launch(void* const* d_in, const int* in_sizes, int n_in,
                              void* d_out, int out_size) {
    const float* x = (const float*)d_in[0];
    const unsigned char* mask = (const unsigned char*)d_in[1];
    const float* coords = (const float*)d_in[2];
    const float* w0a = (const float*)d_in[3];  const float* bn0a = (const float*)d_in[4];
    const float* w0b = (const float*)d_in[5];  const float* bn0b = (const float*)d_in[6];
    const float* wd0 = (const float*)d_in[7];  const float* bnd0 = (const float*)d_in[8];
    const float* w1a = (const float*)d_in[9];  const float* bn1a = (const float*)d_in[10];
    const float* w1b = (const float*)d_in[11]; const float* bn1b = (const float*)d_in[12];
    const float* wd1 = (const float*)d_in[13]; const float* bnd1 = (const float*)d_in[14];
    const float* w2a = (const float*)d_in[15]; const float* bn2a = (const float*)d_in[16];
    const float* w2b = (const float*)d_in[17]; const float* bn2b = (const float*)d_in[18];
    const float* w2c = (const float*)d_in[19]; const float* bn2c = (const float*)d_in[20];

    float *xm, *A0, *B0, *A1, *B1, *A2, *B2, *part, *m0, *m1, *m2, *wt, *bnf, *pl;
    float4* twt;
    cudaGetSymbolAddress((void**)&xm, g_xm);
    cudaGetSymbolAddress((void**)&A0, g_A0);
    cudaGetSymbolAddress((void**)&B0, g_B0);
    cudaGetSymbolAddress((void**)&A1, g_A1);
    cudaGetSymbolAddress((void**)&B1, g_B1);
    cudaGetSymbolAddress((void**)&A2, g_A2);
    cudaGetSymbolAddress((void**)&B2, g_B2);
    cudaGetSymbolAddress((void**)&part, g_part);
    cudaGetSymbolAddress((void**)&m0, g_m0);
    cudaGetSymbolAddress((void**)&m1, g_m1);
    cudaGetSymbolAddress((void**)&m2, g_m2);
    cudaGetSymbolAddress((void**)&wt, g_wt);
    cudaGetSymbolAddress((void**)&twt, g_twt);
    cudaGetSymbolAddress((void**)&bnf, g_bnf);
    cudaGetSymbolAddress((void**)&pl, g_planes);

    // 1-3: probe, merged prep, premask
    probe_k<<<1, 256>>>(mask);
    int prtot = WT_TOTAL + 736 + O_WD0 / 2;
    prep_k<<<(prtot + 255) / 256, 256>>>(w0a, w0b, wd0, w1a, w1b, wd1, w2a, w2b, w2c,
                                         bn0a, bn0b, bnd0, bn1a, bn1b, bnd1, bn2a, bn2b, bn2c,
                                         wt, bnf, twt);
    premask_k<<<(N0 + 255) / 256, 256>>>(x, mask, xm, m0);

    // 4-6: tensor conv0a (ncu target), tensor conv0b, scalar convd0
    tconv_k<16, 32, 64, 32><<<dim3(1, 64, 64), 128>>>(xm, twt + O_W0A / 2, bnf + OB_0A, m0, A0);
    tconv_k<32, 32, 64, 32><<<dim3(1, 64, 64), 128>>>(A0, twt + O_W0B / 2, bnf + OB_0B, m0, B0);
    conv_k<32, 32, 2, 64, 2, 2, 1, 16, false><<<dim3(4, 4, 32), dim3(16, 8)>>>(B0, wt + O_WD0, nullptr, nullptr, part);

    // 7-9: mask downsamples + epi_d0
    down_k<64><<<(N1 + 255) / 256, 256>>>(m0, m1);
    epi_k<32, 32, 2><<<(32 * N1 + 255) / 256, 256>>>(part, bnf + OB_D0, m1, A1);
    down_k<32><<<(N2 + 255) / 256, 256>>>(m1, m2);

    // 10-13: stage 1 @32^3 — scalar v7 (64-thread blocks)
    conv_k<32, 64, 1, 32, 1, 4, 2, 8, true><<<dim3(8, 2, 32), dim3(8, 8)>>>(A1, wt + O_W1A, bnf + OB_1A, m1, B1);
    conv_k<64, 64, 1, 32, 1, 4, 2, 8, true><<<dim3(8, 2, 32), dim3(8, 8)>>>(B1, wt + O_W1B, bnf + OB_1B, m1, A1);
    conv_k<64, 128, 2, 32, 4, 2, 1, 16, false><<<dim3(32, 1, 16), dim3(8, 16)>>>(A1, wt + O_WD1, nullptr, nullptr, part);
    epi_k<128, 16, 4><<<(128 * N2 + 255) / 256, 256>>>(part, bnf + OB_D1, m2, A2);

    // 14-19: stage 2 @16^3 — scalar v7 (split 4, 64-thread blocks)
    conv_k<128, 128, 1, 16, 4, 4, 2, 8, false><<<dim3(64, 1, 8), dim3(4, 8, 2)>>>(A2, wt + O_W2A, nullptr, nullptr, part);
    epi_k<128, 16, 4><<<(128 * N2 + 255) / 256, 256>>>(part, bnf + OB_2A, m2, B2);
    conv_k<128, 128, 1, 16, 4, 4, 2, 8, false><<<dim3(64, 1, 8), dim3(4, 8, 2)>>>(B2, wt + O_W2B, nullptr, nullptr, part);
    epi_k<128, 16, 4><<<(128 * N2 + 255) / 256, 256>>>(part, bnf + OB_2B, m2, A2);
    conv_k<128, 128, 1, 16, 4, 4, 2, 8, false><<<dim3(64, 1, 8), dim3(4, 8, 2)>>>(A2, wt + O_W2C, nullptr, nullptr, part);
    epi_k<128, 16, 4><<<(128 * N2 + 255) / 256, 256>>>(part, bnf + OB_2C, m2, B2);

    // 20-21: triplane + sample
    planes_k<<<(3 * 16 * 16 * 128 + 255) / 256, 256>>>(B2, pl);
    sample_k<<<NPTS / 16, 128>>>(coords, pl, (float*)d_out);
}

// round 16
// speedup vs baseline: 1.5764x; 1.0848x over previous
#include <cuda_runtime.h>
#include <cuda_bf16.h>
#include <cstdint>

// ============================================================================
// SparseConvNet_Triplane v11: conv0a/conv0b as implicit GEMM on
// mma.m16n8k16.bf16 with 3xBF16 hi/lo compensation (half the mma count of
// the tf32 path). Everything else = v10 (scalar v7 convs + epilogues).
// ============================================================================

#define EPSV 1e-3f

static constexpr int N0 = 64 * 64 * 64;
static constexpr int N1 = 32 * 32 * 32;
static constexpr int N2 = 16 * 16 * 16;
static constexpr int NPTS = 65536;

static constexpr int PD0 = 66, PD0_3 = PD0 * PD0 * PD0;
static constexpr int PD1 = 34, PD1_3 = PD1 * PD1 * PD1;
static constexpr int PD2 = 18, PD2_3 = PD2 * PD2 * PD2;

// weight segments (float counts), scalar layout [ci][k][co]
static constexpr int O_W0A = 0;
static constexpr int O_W0B = O_W0A + 16 * 32 * 27;
static constexpr int O_WD0 = O_W0B + 32 * 32 * 27;
static constexpr int O_W1A = O_WD0 + 32 * 32 * 27;
static constexpr int O_W1B = O_W1A + 32 * 64 * 27;
static constexpr int O_WD1 = O_W1B + 64 * 64 * 27;
static constexpr int O_W2A = O_WD1 + 64 * 128 * 27;
static constexpr int O_W2B = O_W2A + 128 * 128 * 27;
static constexpr int O_W2C = O_W2B + 128 * 128 * 27;
static constexpr int WT_TOTAL = O_W2C + 128 * 128 * 27;

// bf16 B-tile segments (float4 counts): [kk][ci/16][co/8] x 32 lanes
static constexpr int TB_W0A = 0;                       // 27*1*4*32 = 3456
static constexpr int TB_W0B = TB_W0A + 27 * 1 * 4 * 32;
static constexpr int TB_TOTAL = TB_W0B + 27 * 2 * 4 * 32;  // +6912 = 10368

// fused BN scale/shift segments
static constexpr int OB_0A = 0;
static constexpr int OB_0B = OB_0A + 2 * 32;
static constexpr int OB_D0 = OB_0B + 2 * 32;
static constexpr int OB_1A = OB_D0 + 2 * 32;
static constexpr int OB_1B = OB_1A + 2 * 64;
static constexpr int OB_D1 = OB_1B + 2 * 64;
static constexpr int OB_2A = OB_D1 + 2 * 128;
static constexpr int OB_2B = OB_2A + 2 * 128;
static constexpr int OB_2C = OB_2B + 2 * 128;

// static scratch; halos of padded buffers never written -> stay 0
__device__ __align__(16) float g_xm[16 * PD0_3];
__device__ __align__(16) float g_A0[32 * PD0_3];
__device__ __align__(16) float g_B0[32 * PD0_3];
__device__ __align__(16) float g_A1[64 * PD1_3];
__device__ __align__(16) float g_B1[64 * PD1_3];
__device__ __align__(16) float g_A2[128 * PD2_3];
__device__ __align__(16) float g_B2[128 * PD2_3];
__device__ __align__(16) float g_part[2097152];
__device__ float g_m0[N0];
__device__ float g_m1[N1];
__device__ float g_m2[N2];
__device__ __align__(16) float g_wt[WT_TOTAL];
__device__ __align__(16) float4 g_twt[TB_TOTAL];       // packed bf16 hi/lo B tiles
__device__ __align__(16) float g_bnf[OB_2C + 2 * 128];
__device__ __align__(16) float g_planes[3 * 16 * 16 * 128];
__device__ int g_mmode;

// ----------------------------------------------------------------------------
// bf16 helpers: split v into bf16 hi + bf16 lo, packed as k-pairs
// ----------------------------------------------------------------------------
__device__ __forceinline__ void split_pack_bf16(float v0, float v1,
                                                uint32_t& hi, uint32_t& lo) {
    __nv_bfloat162 h2 = __floats2bfloat162_rn(v0, v1);     // x=v0 (low), y=v1
    float r0 = v0 - __bfloat162float(h2.x);
    float r1 = v1 - __bfloat162float(h2.y);
    __nv_bfloat162 l2 = __floats2bfloat162_rn(r0, r1);
    hi = *reinterpret_cast<uint32_t*>(&h2);
    lo = *reinterpret_cast<uint32_t*>(&l2);
}
__device__ __forceinline__ void mma_bf16(float* c, const uint32_t* a, uint32_t b0, uint32_t b1) {
    asm("mma.sync.aligned.m16n8k16.row.col.f32.bf16.bf16.f32 "
        "{%0,%1,%2,%3}, {%4,%5,%6,%7}, {%8,%9}, {%0,%1,%2,%3};"
        : "+f"(c[0]), "+f"(c[1]), "+f"(c[2]), "+f"(c[3])
        : "r"(a[0]), "r"(a[1]), "r"(a[2]), "r"(a[3]), "r"(b0), "r"(b1));
}

// ----------------------------------------------------------------------------
// merged prep: scalar wt transpose + BN fusion + bf16 B tiles (w0a,w0b only)
// ----------------------------------------------------------------------------
__global__ void prep_k(const float* __restrict__ w0a, const float* __restrict__ w0b,
                       const float* __restrict__ wd0, const float* __restrict__ w1a,
                       const float* __restrict__ w1b, const float* __restrict__ wd1,
                       const float* __restrict__ w2a, const float* __restrict__ w2b,
                       const float* __restrict__ w2c,
                       const float* __restrict__ b0a, const float* __restrict__ b0b,
                       const float* __restrict__ bd0, const float* __restrict__ b1a,
                       const float* __restrict__ b1b, const float* __restrict__ bd1,
                       const float* __restrict__ b2a, const float* __restrict__ b2b,
                       const float* __restrict__ b2c,
                       float* __restrict__ wt, float* __restrict__ bnf,
                       float4* __restrict__ twt) {
    int i = blockIdx.x * blockDim.x + threadIdx.x;
    if (i < WT_TOTAL) {
        const float* src; int off, cin, cout;
        if      (i < O_W0B) { src = w0a; off = O_W0A; cin = 16;  cout = 32; }
        else if (i < O_WD0) { src = w0b; off = O_W0B; cin = 32;  cout = 32; }
        else if (i < O_W1A) { src = wd0; off = O_WD0; cin = 32;  cout = 32; }
        else if (i < O_W1B) { src = w1a; off = O_W1A; cin = 32;  cout = 64; }
        else if (i < O_WD1) { src = w1b; off = O_W1B; cin = 64;  cout = 64; }
        else if (i < O_W2A) { src = wd1; off = O_WD1; cin = 64;  cout = 128; }
        else if (i < O_W2B) { src = w2a; off = O_W2A; cin = 128; cout = 128; }
        else if (i < O_W2C) { src = w2b; off = O_W2B; cin = 128; cout = 128; }
        else                { src = w2c; off = O_W2C; cin = 128; cout = 128; }
        int r = i - off;
        int co = r % cout;
        int k  = (r / cout) % 27;
        int ci = r / (cout * 27);
        wt[i] = src[(co * cin + ci) * 27 + k];
    } else if (i < WT_TOTAL + 736) {
        int j = i - WT_TOTAL;
        const float* bn; int off, C, c;
        if      (j < 32)  { bn = b0a; off = OB_0A; C = 32;  c = j; }
        else if (j < 64)  { bn = b0b; off = OB_0B; C = 32;  c = j - 32; }
        else if (j < 96)  { bn = bd0; off = OB_D0; C = 32;  c = j - 64; }
        else if (j < 160) { bn = b1a; off = OB_1A; C = 64;  c = j - 96; }
        else if (j < 224) { bn = b1b; off = OB_1B; C = 64;  c = j - 160; }
        else if (j < 352) { bn = bd1; off = OB_D1; C = 128; c = j - 224; }
        else if (j < 480) { bn = b2a; off = OB_2A; C = 128; c = j - 352; }
        else if (j < 608) { bn = b2b; off = OB_2B; C = 128; c = j - 480; }
        else              { bn = b2c; off = OB_2C; C = 128; c = j - 608; }
        float g = bn[c], b = bn[C + c], mu = bn[2 * C + c], v = bn[3 * C + c];
        float s = g * rsqrtf(v + EPSV);
        bnf[off + 2 * c] = s;
        bnf[off + 2 * c + 1] = b - s * mu;
    } else {
        int i2 = i - (WT_TOTAL + 736);            // float4 index in twt
        if (i2 >= TB_TOTAL) return;
        const float* src; int off, cin, cout;
        if (i2 < TB_W0B) { src = w0a; off = TB_W0A; cin = 16; cout = 32; }
        else             { src = w0b; off = TB_W0B; cin = 32; cout = 32; }
        int r4 = i2 - off;
        int lane = r4 & 31;
        int blk = r4 >> 5;
        int ntt = cout / 8, cs16 = cin / 16;
        int t = blk % ntt;
        int s16 = (blk / ntt) % cs16;
        int kk = blk / (ntt * cs16);
        int tg = lane & 3, gid = lane >> 2;
        int ci0 = s16 * 16 + 2 * tg;              // k-pair base (low)
        int co = t * 8 + gid;
        float w00 = src[(co * cin + ci0) * 27 + kk];
        float w01 = src[(co * cin + ci0 + 1) * 27 + kk];
        float w10 = src[(co * cin + ci0 + 8) * 27 + kk];
        float w11 = src[(co * cin + ci0 + 9) * 27 + kk];
        uint32_t b0h, b0l, b1h, b1l;
        split_pack_bf16(w00, w01, b0h, b0l);
        split_pack_bf16(w10, w11, b1h, b1l);
        twt[i2] = make_float4(__uint_as_float(b0h), __uint_as_float(b1h),
                              __uint_as_float(b0l), __uint_as_float(b1l));
    }
}

// ----------------------------------------------------------------------------
// mask dtype probe (mode 0=u8 bool, 1=i32 bool, 2=f32, 3=bf16)
// ----------------------------------------------------------------------------
__global__ void probe_k(const unsigned char* __restrict__ b) {
    __shared__ int s_off1, s_big;
    if (threadIdx.x == 0) { s_off1 = 0; s_big = 0; }
    __syncthreads();
    int off1 = 0, big = 0;
    for (int i = threadIdx.x; i < 16384; i += blockDim.x) {
        unsigned char b0 = b[4 * i + 0], b1 = b[4 * i + 1];
        unsigned char b2 = b[4 * i + 2], b3 = b[4 * i + 3];
        if (b1) off1++;
        if (b0 > 1 || b1 > 1 || b2 > 1 || b3 > 1) big++;
    }
    atomicAdd(&s_off1, off1);
    atomicAdd(&s_big, big);
    __syncthreads();
    if (threadIdx.x == 0)
        g_mmode = (s_big == 0) ? ((s_off1 > 0) ? 0 : 1) : ((s_off1 > 0) ? 3 : 2);
}

__device__ __forceinline__ float mask_at(const unsigned char* b, int v, int mode) {
    if (mode == 0) return b[v] ? 1.f : 0.f;
    if (mode == 1) return ((const int*)b)[v] ? 1.f : 0.f;
    if (mode == 2) return (((const float*)b)[v] != 0.f) ? 1.f : 0.f;
    return (__bfloat162float(((const __nv_bfloat16*)b)[v]) != 0.f) ? 1.f : 0.f;
}

__global__ void premask_k(const float* __restrict__ x, const unsigned char* __restrict__ mb,
                          float* __restrict__ xm, float* __restrict__ m0) {
    int v = blockIdx.x * blockDim.x + threadIdx.x;
    if (v >= N0) return;
    int mode = g_mmode;
    float m = mask_at(mb, v, mode);
    m0[v] = m;
    int xx = v & 63, yy = (v >> 6) & 63, zz = v >> 12;
    int pidx = ((zz + 1) * PD0 + (yy + 1)) * PD0 + (xx + 1);
#pragma unroll
    for (int ci = 0; ci < 16; ci++) xm[ci * PD0_3 + pidx] = x[ci * N0 + v] * m;
}

template <int DIN>
__global__ void down_k(const float* __restrict__ mi, float* __restrict__ mo) {
    constexpr int DOUT = DIN / 2;
    int id = blockIdx.x * blockDim.x + threadIdx.x;
    if (id >= DOUT * DOUT * DOUT) return;
    int x = id % DOUT, y = (id / DOUT) % DOUT, z = id / (DOUT * DOUT);
    float m = 0.f;
#pragma unroll
    for (int dz = -1; dz <= 1; dz++) {
        int zz = 2 * z + dz; if ((unsigned)zz >= DIN) continue;
#pragma unroll
        for (int dy = -1; dy <= 1; dy++) {
            int yy = 2 * y + dy; if ((unsigned)yy >= DIN) continue;
#pragma unroll
            for (int dx = -1; dx <= 1; dx++) {
                int xx = 2 * x + dx; if ((unsigned)xx >= DIN) continue;
                m = fmaxf(m, mi[(zz * DIN + yy) * DIN + xx]);
            }
        }
    }
    mo[id] = m;
}

// ----------------------------------------------------------------------------
// bf16 tensor-core stride-1 conv (64^3 layers only): 3xBF16 on m16n8k16.
// A k-pairs = adjacent channel planes; split accumulators for ILP.
// grid = (COUT/NCH, 64, 64); CTA 4 warps; warp = one 16-voxel m-tile.
// ----------------------------------------------------------------------------
template <int CIN, int COUT, int NCH>
__global__ __launch_bounds__(128) void tconv_k(const float* __restrict__ in,
                                               const float4* __restrict__ wb,
                                               const float* __restrict__ bnf,
                                               const float* __restrict__ mask,
                                               float* __restrict__ out) {
    constexpr int DIN = 64;
    constexpr int PDI = DIN + 2;
    constexpr int PDI3 = PDI * PDI * PDI;
    constexpr int PDO3 = PDI3;
    constexpr int NT = NCH / 8;
    constexpr int CS16 = CIN / 16;
    constexpr int NTT = COUT / 8;

    const int warp = threadIdx.x >> 5, lane = threadIdx.x & 31;
    const int gid = lane >> 2, tg = lane & 3;
    const int nc = blockIdx.x;
    const int z = blockIdx.z;
    const int ym = blockIdx.y;
    const int xt = warp * 16;

    float chi[NT][4], cco[NT][4];
#pragma unroll
    for (int t = 0; t < NT; t++)
#pragma unroll
        for (int j = 0; j < 4; j++) { chi[t][j] = 0.f; cco[t][j] = 0.f; }

    const float* inb = in + 2 * tg * PDI3;         // k-pair channel base
    const float4* bp = wb + nc * NT * 32 + lane;   // advances linearly

#pragma unroll 1
    for (int dz = 0; dz < 3; dz++) {
#pragma unroll
        for (int dy = 0; dy < 3; dy++) {
            const float* rp = inb + ((z + dz) * PDI + (ym + dy)) * PDI + xt + gid;
#pragma unroll
            for (int dx = 0; dx < 3; dx++) {
                const float* ap = rp + dx;
#pragma unroll
                for (int s = 0; s < CS16; s++) {
                    // rows gid / gid+8, channel pairs (2tg,2tg+1) and (+8,+9)
                    float v00 = __ldg(ap);
                    float v01 = __ldg(ap + PDI3);
                    float v10 = __ldg(ap + 8);
                    float v11 = __ldg(ap + PDI3 + 8);
                    float v20 = __ldg(ap + 8 * PDI3);
                    float v21 = __ldg(ap + 9 * PDI3);
                    float v30 = __ldg(ap + 8 * PDI3 + 8);
                    float v31 = __ldg(ap + 9 * PDI3 + 8);
                    uint32_t ah[4], al[4];
                    split_pack_bf16(v00, v01, ah[0], al[0]);
                    split_pack_bf16(v10, v11, ah[1], al[1]);
                    split_pack_bf16(v20, v21, ah[2], al[2]);
                    split_pack_bf16(v30, v31, ah[3], al[3]);
#pragma unroll
                    for (int t = 0; t < NT; t++) {
                        float4 bb = __ldg(bp + t * 32);
                        uint32_t bh0 = __float_as_uint(bb.x), bh1 = __float_as_uint(bb.y);
                        uint32_t bl0 = __float_as_uint(bb.z), bl1 = __float_as_uint(bb.w);
                        mma_bf16(chi[t], ah, bh0, bh1);
                        mma_bf16(cco[t], ah, bl0, bl1);
                        mma_bf16(cco[t], al, bh0, bh1);
                    }
                    ap += 16 * PDI3;
                    bp += NTT * 32;
                }
            }
        }
    }

    int voxu = (z * DIN + ym) * DIN + xt;
    float mv0 = mask[voxu + gid];
    float mv1 = mask[voxu + gid + 8];
    int pv = ((z + 1) * PDI + (ym + 1)) * PDI + (xt + 1) + gid;
#pragma unroll
    for (int t = 0; t < NT; t++) {
        int c0 = nc * NCH + t * 8 + 2 * tg;
        float4 b4 = *reinterpret_cast<const float4*>(bnf + 2 * c0);
        float* o0 = out + c0 * PDO3 + pv;
        float* o1 = o0 + PDO3;
        float r0 = chi[t][0] + cco[t][0];
        float r1 = chi[t][1] + cco[t][1];
        float r2 = chi[t][2] + cco[t][2];
        float r3 = chi[t][3] + cco[t][3];
        o0[0] = fmaxf(fmaf(b4.x, r0, b4.y), 0.f) * mv0;
        o1[0] = fmaxf(fmaf(b4.z, r1, b4.w), 0.f) * mv0;
        o0[8] = fmaxf(fmaf(b4.x, r2, b4.y), 0.f) * mv1;
        o1[8] = fmaxf(fmaf(b4.z, r3, b4.w), 0.f) * mv1;
    }
}

// ----------------------------------------------------------------------------
// scalar conv (v7) — stage 1, stage 2, stride-2 layers
// ----------------------------------------------------------------------------
template <int CIN, int COUT, int STRIDE, int DIN, int SPLIT, int XT, int YT, int CH, bool FUSE>
__global__ __launch_bounds__(128, 4) void conv_k(const float* __restrict__ in,
                                                 const float* __restrict__ wt,
                                                 const float* __restrict__ bnf,
                                                 const float* __restrict__ mask,
                                                 float* __restrict__ out) {
    constexpr int DOUT = DIN / STRIDE;
    constexpr int PDI = DIN + 2;
    constexpr int PDI3 = PDI * PDI * PDI;
    constexpr int PDO = DOUT + 2;
    constexpr int PDO3 = PDO * PDO * PDO;
    constexpr int CHUNKS = COUT / CH;
    constexpr int CIB = CIN / SPLIT;
    constexpr int W = (XT - 1) * STRIDE + 3;
    constexpr int ROWS = (YT - 1) * STRIDE + 3;

    int tx = threadIdx.x, ty = threadIdx.y;
    int chunk = blockIdx.x % CHUNKS;
    int split = blockIdx.x / CHUNKS;
    int cb = chunk * CH;
    int y0 = (blockIdx.y * blockDim.y + ty) * YT;
    int z = blockIdx.z * blockDim.z + threadIdx.z;
    int x0 = XT * tx;

    float acc[YT * XT * CH];
#pragma unroll
    for (int i = 0; i < YT * XT * CH; i++) acc[i] = 0.f;

    const float* base = in + split * CIB * PDI3
                        + (z * STRIDE * PDI + y0 * STRIDE) * PDI + x0 * STRIDE;
    const float* wp = wt + (split * CIB * 27) * COUT + cb;

    for (int ci = 0; ci < CIB; ci++) {
#pragma unroll
        for (int dz = 0; dz < 3; dz++) {
            float v[ROWS][W];
#pragma unroll
            for (int r = 0; r < ROWS; r++) {
                const float* rp = base + (dz * PDI + r) * PDI;
                const float2* rp2 = reinterpret_cast<const float2*>(rp);
#pragma unroll
                for (int i = 0; i < W / 2; i++) {
                    float2 t = __ldg(rp2 + i);
                    v[r][2 * i] = t.x;
                    v[r][2 * i + 1] = t.y;
                }
                if (W & 1) v[r][W - 1] = __ldg(rp + W - 1);
            }
#pragma unroll
            for (int dy = 0; dy < 3; dy++)
#pragma unroll
                for (int dx = 0; dx < 3; dx++) {
                    const int k = (dz * 3 + dy) * 3 + dx;
                    const float4* w4 = reinterpret_cast<const float4*>(wp + k * COUT);
#pragma unroll
                    for (int j = 0; j < CH / 4; j++) {
                        float4 ww = __ldg(w4 + j);
#pragma unroll
                        for (int yt = 0; yt < YT; yt++)
#pragma unroll
                            for (int xt = 0; xt < XT; xt++) {
                                float a = v[yt * STRIDE + dy][xt * STRIDE + dx];
                                int o = (yt * XT + xt) * CH + 4 * j;
                                acc[o + 0] = fmaf(a, ww.x, acc[o + 0]);
                                acc[o + 1] = fmaf(a, ww.y, acc[o + 1]);
                                acc[o + 2] = fmaf(a, ww.z, acc[o + 2]);
                                acc[o + 3] = fmaf(a, ww.w, acc[o + 3]);
                            }
                    }
                }
        }
        base += PDI3;
        wp += 27 * COUT;
    }

    if (FUSE) {
#pragma unroll
        for (int yt = 0; yt < YT; yt++) {
            int voxu = (z * DOUT + y0 + yt) * DOUT + x0;
            float mm[XT];
#pragma unroll
            for (int xt = 0; xt < XT; xt++) mm[xt] = mask[voxu + xt];
            int pvox = ((z + 1) * PDO + (y0 + yt + 1)) * PDO + (x0 + 1);
#pragma unroll
            for (int i = 0; i < CH; i++) {
                int c = cb + i;
                float s = __ldg(bnf + 2 * c);
                float t = __ldg(bnf + 2 * c + 1);
#pragma unroll
                for (int xt = 0; xt < XT; xt++)
                    out[c * PDO3 + pvox + xt] =
                        fmaxf(fmaf(s, acc[(yt * XT + xt) * CH + i], t), 0.f) * mm[xt];
            }
        }
    } else {
        constexpr int N = DOUT * DOUT * DOUT;
#pragma unroll
        for (int yt = 0; yt < YT; yt++) {
            int vox = (z * DOUT + y0 + yt) * DOUT + x0;
#pragma unroll
            for (int i = 0; i < CH; i++) {
                int c = cb + i;
#pragma unroll
                for (int xt = 0; xt < XT; xt++)
                    out[(split * COUT + c) * N + vox + xt] = acc[(yt * XT + xt) * CH + i];
            }
        }
    }
}

// epilogue for split convs
template <int COUT, int DOUT, int SPLIT>
__global__ void epi_k(const float* __restrict__ part, const float* __restrict__ bnf,
                      const float* __restrict__ mask, float* __restrict__ out) {
    constexpr int N = DOUT * DOUT * DOUT;
    constexpr int PDO = DOUT + 2;
    constexpr int PDO3 = PDO * PDO * PDO;
    int id = blockIdx.x * blockDim.x + threadIdx.x;
    if (id >= COUT * N) return;
    int vox = id % N, c = id / N;
    float a = 0.f;
#pragma unroll
    for (int s = 0; s < SPLIT; s++) a += part[(s * COUT + c) * N + vox];
    float sc = __ldg(bnf + 2 * c), t = __ldg(bnf + 2 * c + 1);
    int x = vox % DOUT, y = (vox / DOUT) % DOUT, z = vox / (DOUT * DOUT);
    out[c * PDO3 + ((z + 1) * PDO + (y + 1)) * PDO + (x + 1)] =
        fmaxf(fmaf(sc, a, t), 0.f) * mask[vox];
}

// ----------------------------------------------------------------------------
// triplane means + sampler
// ----------------------------------------------------------------------------
__global__ void planes_k(const float* __restrict__ f, float* __restrict__ pl) {
    int id = blockIdx.x * blockDim.x + threadIdx.x;
    if (id >= 3 * 16 * 16 * 128) return;
    int c = id & 127;
    int rem = id >> 7;
    int b = rem & 15;
    int a = (rem >> 4) & 15;
    int t = rem >> 8;
    const float* fc = f + c * PD2_3;
    float s = 0.f;
    if (t == 0) {
#pragma unroll
        for (int z = 0; z < 16; z++) s += fc[((z + 1) * PD2 + (a + 1)) * PD2 + (b + 1)];
    } else if (t == 1) {
#pragma unroll
        for (int xx = 0; xx < 16; xx++) s += fc[((a + 1) * PD2 + (b + 1)) * PD2 + (xx + 1)];
    } else {
#pragma unroll
        for (int yy = 0; yy < 16; yy++) s += fc[((a + 1) * PD2 + (yy + 1)) * PD2 + (b + 1)];
    }
    pl[t * (16 * 16 * 128) + (a * 16 + b) * 128 + c] = s * (1.f / 16.f);
}

__device__ __forceinline__ float samp2d(const float* __restrict__ img, float gx, float gy, int c) {
    float ix = (gx + 1.f) * 0.5f * 15.f;
    float iy = (gy + 1.f) * 0.5f * 15.f;
    float x0f = floorf(ix), y0f = floorf(iy);
    int x0 = (int)x0f, y0 = (int)y0f;
    float wx = ix - x0f, wy = iy - y0f;
    float r = 0.f;
#pragma unroll
    for (int dy = 0; dy < 2; dy++)
#pragma unroll
        for (int dx = 0; dx < 2; dx++) {
            int xx = x0 + dx, yy = y0 + dy;
            float w = (dy ? wy : 1.f - wy) * (dx ? wx : 1.f - wx);
            bool ok = ((unsigned)xx < 16u) && ((unsigned)yy < 16u);
            int xc = min(max(xx, 0), 15), yc = min(max(yy, 0), 15);
            float v = __ldg(img + (yc * 16 + xc) * 128 + c);
            r += v * (ok ? w : 0.f);
        }
    return r;
}

__global__ void sample_k(const float* __restrict__ coords, const float* __restrict__ planes,
                         float* __restrict__ out) {
    constexpr int PTS = 16;
    int c = threadIdx.x;  // 128
    int p0 = blockIdx.x * PTS;
#pragma unroll 1
    for (int i = 0; i < PTS; i++) {
        int p = p0 + i;
        float c0 = __ldg(coords + 3 * p + 0);
        float c1 = __ldg(coords + 3 * p + 1);
        float c2 = __ldg(coords + 3 * p + 2);
        float s = samp2d(planes + 0 * (16 * 16 * 128), c0, c1, c)
                + samp2d(planes + 1 * (16 * 16 * 128), c1, c2, c)
                + samp2d(planes + 2 * (16 * 16 * 128), c0, c2, c);
        out[(size_t)p * 128 + c] = s;
    }
}

// ----------------------------------------------------------------------------
// launch — launch #4 is tconv0a (ncu target)
// ----------------------------------------------------------------------------
extern "C" void kernel_launch(void* const* d_in, const int* in_sizes, int n_in,
                              void* d_out, int out_size) {
    const float* x = (const float*)d_in[0];
    const unsigned char* mask = (const unsigned char*)d_in[1];
    const float* coords = (const float*)d_in[2];
    const float* w0a = (const float*)d_in[3];  const float* bn0a = (const float*)d_in[4];
    const float* w0b = (const float*)d_in[5];  const float* bn0b = (const float*)d_in[6];
    const float* wd0 = (const float*)d_in[7];  const float* bnd0 = (const float*)d_in[8];
    const float* w1a = (const float*)d_in[9];  const float* bn1a = (const float*)d_in[10];
    const float* w1b = (const float*)d_in[11]; const float* bn1b = (const float*)d_in[12];
    const float* wd1 = (const float*)d_in[13]; const float* bnd1 = (const float*)d_in[14];
    const float* w2a = (const float*)d_in[15]; const float* bn2a = (const float*)d_in[16];
    const float* w2b = (const float*)d_in[17]; const float* bn2b = (const float*)d_in[18];
    const float* w2c = (const float*)d_in[19]; const float* bn2c = (const float*)d_in[20];

    float *xm, *A0, *B0, *A1, *B1, *A2, *B2, *part, *m0, *m1, *m2, *wt, *bnf, *pl;
    float4* twt;
    cudaGetSymbolAddress((void**)&xm, g_xm);
    cudaGetSymbolAddress((void**)&A0, g_A0);
    cudaGetSymbolAddress((void**)&B0, g_B0);
    cudaGetSymbolAddress((void**)&A1, g_A1);
    cudaGetSymbolAddress((void**)&B1, g_B1);
    cudaGetSymbolAddress((void**)&A2, g_A2);
    cudaGetSymbolAddress((void**)&B2, g_B2);
    cudaGetSymbolAddress((void**)&part, g_part);
    cudaGetSymbolAddress((void**)&m0, g_m0);
    cudaGetSymbolAddress((void**)&m1, g_m1);
    cudaGetSymbolAddress((void**)&m2, g_m2);
    cudaGetSymbolAddress((void**)&wt, g_wt);
    cudaGetSymbolAddress((void**)&twt, g_twt);
    cudaGetSymbolAddress((void**)&bnf, g_bnf);
    cudaGetSymbolAddress((void**)&pl, g_planes);

    // 1-3: probe, merged prep, premask
    probe_k<<<1, 256>>>(mask);
    int prtot = WT_TOTAL + 736 + TB_TOTAL;
    prep_k<<<(prtot + 255) / 256, 256>>>(w0a, w0b, wd0, w1a, w1b, wd1, w2a, w2b, w2c,
                                         bn0a, bn0b, bnd0, bn1a, bn1b, bnd1, bn2a, bn2b, bn2c,
                                         wt, bnf, twt);
    premask_k<<<(N0 + 255) / 256, 256>>>(x, mask, xm, m0);

    // 4-6: bf16 tensor conv0a (ncu target), conv0b, scalar convd0
    tconv_k<16, 32, 32><<<dim3(1, 64, 64), 128>>>(xm, twt + TB_W0A, bnf + OB_0A, m0, A0);
    tconv_k<32, 32, 32><<<dim3(1, 64, 64), 128>>>(A0, twt + TB_W0B, bnf + OB_0B, m0, B0);
    conv_k<32, 32, 2, 64, 2, 2, 1, 16, false><<<dim3(4, 4, 32), dim3(16, 8)>>>(B0, wt + O_WD0, nullptr, nullptr, part);

    // 7-9: mask downsamples + epi_d0
    down_k<64><<<(N1 + 255) / 256, 256>>>(m0, m1);
    epi_k<32, 32, 2><<<(32 * N1 + 255) / 256, 256>>>(part, bnf + OB_D0, m1, A1);
    down_k<32><<<(N2 + 255) / 256, 256>>>(m1, m2);

    // 10-13: stage 1 @32^3 — scalar v7 (64-thread blocks)
    conv_k<32, 64, 1, 32, 1, 4, 2, 8, true><<<dim3(8, 2, 32), dim3(8, 8)>>>(A1, wt + O_W1A, bnf + OB_1A, m1, B1);
    conv_k<64, 64, 1, 32, 1, 4, 2, 8, true><<<dim3(8, 2, 32), dim3(8, 8)>>>(B1, wt + O_W1B, bnf + OB_1B, m1, A1);
    conv_k<64, 128, 2, 32, 4, 2, 1, 16, false><<<dim3(32, 1, 16), dim3(8, 16)>>>(A1, wt + O_WD1, nullptr, nullptr, part);
    epi_k<128, 16, 4><<<(128 * N2 + 255) / 256, 256>>>(part, bnf + OB_D1, m2, A2);

    // 14-19: stage 2 @16^3 — scalar v7 (split 4, 64-thread blocks)
    conv_k<128, 128, 1, 16, 4, 4, 2, 8, false><<<dim3(64, 1, 8), dim3(4, 8, 2)>>>(A2, wt + O_W2A, nullptr, nullptr, part);
    epi_k<128, 16, 4><<<(128 * N2 + 255) / 256, 256>>>(part, bnf + OB_2A, m2, B2);
    conv_k<128, 128, 1, 16, 4, 4, 2, 8, false><<<dim3(64, 1, 8), dim3(4, 8, 2)>>>(B2, wt + O_W2B, nullptr, nullptr, part);
    epi_k<128, 16, 4><<<(128 * N2 + 255) / 256, 256>>>(part, bnf + OB_2B, m2, A2);
    conv_k<128, 128, 1, 16, 4, 4, 2, 8, false><<<dim3(64, 1, 8), dim3(4, 8, 2)>>>(A2, wt + O_W2C, nullptr, nullptr, part);
    epi_k<128, 16, 4><<<(128 * N2 + 255) / 256, 256>>>(part, bnf + OB_2C, m2, B2);

    // 20-21: triplane + sample
    planes_k<<<(3 * 16 * 16 * 128 + 255) / 256, 256>>>(B2, pl);
    sample_k<<<NPTS / 16, 128>>>(coords, pl, (float*)d_out);
}

// round 17
// speedup vs baseline: 1.6781x; 1.0645x over previous
#include <cuda_runtime.h>
#include <cuda_bf16.h>
#include <cstdint>

// ============================================================================
// SparseConvNet_Triplane v12: ALL stride-1 convs as 3xBF16 m16n8k16 implicit
// GEMM (fused BN epilogues, no stage-2 split/epi). Stride-2 convs scalar.
// ============================================================================

#define EPSV 1e-3f

static constexpr int N0 = 64 * 64 * 64;
static constexpr int N1 = 32 * 32 * 32;
static constexpr int N2 = 16 * 16 * 16;
static constexpr int NPTS = 65536;

static constexpr int PD0 = 66, PD0_3 = PD0 * PD0 * PD0;
static constexpr int PD1 = 34, PD1_3 = PD1 * PD1 * PD1;
static constexpr int PD2 = 18, PD2_3 = PD2 * PD2 * PD2;

// scalar weight segments (float counts), layout [ci][k][co] — stride-2 only use
static constexpr int O_W0A = 0;
static constexpr int O_W0B = O_W0A + 16 * 32 * 27;
static constexpr int O_WD0 = O_W0B + 32 * 32 * 27;
static constexpr int O_W1A = O_WD0 + 32 * 32 * 27;
static constexpr int O_W1B = O_W1A + 32 * 64 * 27;
static constexpr int O_WD1 = O_W1B + 64 * 64 * 27;
static constexpr int O_W2A = O_WD1 + 64 * 128 * 27;
static constexpr int O_W2B = O_W2A + 128 * 128 * 27;
static constexpr int O_W2C = O_W2B + 128 * 128 * 27;
static constexpr int WT_TOTAL = O_W2C + 128 * 128 * 27;

// bf16 B-tile segments (float4 counts): per layer 27*(CIN/16)*(COUT/8)*32
static constexpr int TB_W0A = 0;
static constexpr int TB_W0B = TB_W0A + 27 * 1 * 4 * 32;    // 3456
static constexpr int TB_W1A = TB_W0B + 27 * 2 * 4 * 32;    // +6912
static constexpr int TB_W1B = TB_W1A + 27 * 2 * 8 * 32;    // +13824
static constexpr int TB_W2A = TB_W1B + 27 * 4 * 8 * 32;    // +27648
static constexpr int TB_W2B = TB_W2A + 27 * 8 * 16 * 32;   // +110592
static constexpr int TB_W2C = TB_W2B + 27 * 8 * 16 * 32;
static constexpr int TB_TOTAL = TB_W2C + 27 * 8 * 16 * 32; // 383616 float4

// fused BN scale/shift segments
static constexpr int OB_0A = 0;
static constexpr int OB_0B = OB_0A + 2 * 32;
static constexpr int OB_D0 = OB_0B + 2 * 32;
static constexpr int OB_1A = OB_D0 + 2 * 32;
static constexpr int OB_1B = OB_1A + 2 * 64;
static constexpr int OB_D1 = OB_1B + 2 * 64;
static constexpr int OB_2A = OB_D1 + 2 * 128;
static constexpr int OB_2B = OB_2A + 2 * 128;
static constexpr int OB_2C = OB_2B + 2 * 128;

// static scratch; halos of padded buffers never written -> stay 0
__device__ __align__(16) float g_xm[16 * PD0_3];
__device__ __align__(16) float g_A0[32 * PD0_3];
__device__ __align__(16) float g_B0[32 * PD0_3];
__device__ __align__(16) float g_A1[64 * PD1_3];
__device__ __align__(16) float g_B1[64 * PD1_3];
__device__ __align__(16) float g_A2[128 * PD2_3];
__device__ __align__(16) float g_B2[128 * PD2_3];
__device__ __align__(16) float g_part[2097152];
__device__ float g_m0[N0];
__device__ float g_m1[N1];
__device__ float g_m2[N2];
__device__ __align__(16) float g_wt[WT_TOTAL];
__device__ __align__(16) float4 g_twt[TB_TOTAL];
__device__ __align__(16) float g_bnf[OB_2C + 2 * 128];
__device__ __align__(16) float g_planes[3 * 16 * 16 * 128];
__device__ int g_mmode;

// ----------------------------------------------------------------------------
// bf16 helpers
// ----------------------------------------------------------------------------
__device__ __forceinline__ void split_pack_bf16(float v0, float v1,
                                                uint32_t& hi, uint32_t& lo) {
    __nv_bfloat162 h2 = __floats2bfloat162_rn(v0, v1);
    float r0 = v0 - __bfloat162float(h2.x);
    float r1 = v1 - __bfloat162float(h2.y);
    __nv_bfloat162 l2 = __floats2bfloat162_rn(r0, r1);
    hi = *reinterpret_cast<uint32_t*>(&h2);
    lo = *reinterpret_cast<uint32_t*>(&l2);
}
__device__ __forceinline__ void mma_bf16(float* c, const uint32_t* a, uint32_t b0, uint32_t b1) {
    asm("mma.sync.aligned.m16n8k16.row.col.f32.bf16.bf16.f32 "
        "{%0,%1,%2,%3}, {%4,%5,%6,%7}, {%8,%9}, {%0,%1,%2,%3};"
        : "+f"(c[0]), "+f"(c[1]), "+f"(c[2]), "+f"(c[3])
        : "r"(a[0]), "r"(a[1]), "r"(a[2]), "r"(a[3]), "r"(b0), "r"(b1));
}

// ----------------------------------------------------------------------------
// merged prep: scalar wt transpose + BN fusion + bf16 B tiles (all stride-1)
// ----------------------------------------------------------------------------
__global__ void prep_k(const float* __restrict__ w0a, const float* __restrict__ w0b,
                       const float* __restrict__ wd0, const float* __restrict__ w1a,
                       const float* __restrict__ w1b, const float* __restrict__ wd1,
                       const float* __restrict__ w2a, const float* __restrict__ w2b,
                       const float* __restrict__ w2c,
                       const float* __restrict__ b0a, const float* __restrict__ b0b,
                       const float* __restrict__ bd0, const float* __restrict__ b1a,
                       const float* __restrict__ b1b, const float* __restrict__ bd1,
                       const float* __restrict__ b2a, const float* __restrict__ b2b,
                       const float* __restrict__ b2c,
                       float* __restrict__ wt, float* __restrict__ bnf,
                       float4* __restrict__ twt) {
    int i = blockIdx.x * blockDim.x + threadIdx.x;
    if (i < WT_TOTAL) {
        const float* src; int off, cin, cout;
        if      (i < O_W0B) { src = w0a; off = O_W0A; cin = 16;  cout = 32; }
        else if (i < O_WD0) { src = w0b; off = O_W0B; cin = 32;  cout = 32; }
        else if (i < O_W1A) { src = wd0; off = O_WD0; cin = 32;  cout = 32; }
        else if (i < O_W1B) { src = w1a; off = O_W1A; cin = 32;  cout = 64; }
        else if (i < O_WD1) { src = w1b; off = O_W1B; cin = 64;  cout = 64; }
        else if (i < O_W2A) { src = wd1; off = O_WD1; cin = 64;  cout = 128; }
        else if (i < O_W2B) { src = w2a; off = O_W2A; cin = 128; cout = 128; }
        else if (i < O_W2C) { src = w2b; off = O_W2B; cin = 128; cout = 128; }
        else                { src = w2c; off = O_W2C; cin = 128; cout = 128; }
        int r = i - off;
        int co = r % cout;
        int k  = (r / cout) % 27;
        int ci = r / (cout * 27);
        wt[i] = src[(co * cin + ci) * 27 + k];
    } else if (i < WT_TOTAL + 736) {
        int j = i - WT_TOTAL;
        const float* bn; int off, C, c;
        if      (j < 32)  { bn = b0a; off = OB_0A; C = 32;  c = j; }
        else if (j < 64)  { bn = b0b; off = OB_0B; C = 32;  c = j - 32; }
        else if (j < 96)  { bn = bd0; off = OB_D0; C = 32;  c = j - 64; }
        else if (j < 160) { bn = b1a; off = OB_1A; C = 64;  c = j - 96; }
        else if (j < 224) { bn = b1b; off = OB_1B; C = 64;  c = j - 160; }
        else if (j < 352) { bn = bd1; off = OB_D1; C = 128; c = j - 224; }
        else if (j < 480) { bn = b2a; off = OB_2A; C = 128; c = j - 352; }
        else if (j < 608) { bn = b2b; off = OB_2B; C = 128; c = j - 480; }
        else              { bn = b2c; off = OB_2C; C = 128; c = j - 608; }
        float g = bn[c], b = bn[C + c], mu = bn[2 * C + c], v = bn[3 * C + c];
        float s = g * rsqrtf(v + EPSV);
        bnf[off + 2 * c] = s;
        bnf[off + 2 * c + 1] = b - s * mu;
    } else {
        int i2 = i - (WT_TOTAL + 736);
        if (i2 >= TB_TOTAL) return;
        const float* src; int off, cin, cout;
        if      (i2 < TB_W0B) { src = w0a; off = TB_W0A; cin = 16;  cout = 32; }
        else if (i2 < TB_W1A) { src = w0b; off = TB_W0B; cin = 32;  cout = 32; }
        else if (i2 < TB_W1B) { src = w1a; off = TB_W1A; cin = 32;  cout = 64; }
        else if (i2 < TB_W2A) { src = w1b; off = TB_W1B; cin = 64;  cout = 64; }
        else if (i2 < TB_W2B) { src = w2a; off = TB_W2A; cin = 128; cout = 128; }
        else if (i2 < TB_W2C) { src = w2b; off = TB_W2B; cin = 128; cout = 128; }
        else                  { src = w2c; off = TB_W2C; cin = 128; cout = 128; }
        int r4 = i2 - off;
        int lane = r4 & 31;
        int blk = r4 >> 5;
        int ntt = cout / 8, cs16 = cin / 16;
        int t = blk % ntt;
        int s16 = (blk / ntt) % cs16;
        int kk = blk / (ntt * cs16);
        int tg = lane & 3, gid = lane >> 2;
        int ci0 = s16 * 16 + 2 * tg;
        int co = t * 8 + gid;
        float w00 = src[(co * cin + ci0) * 27 + kk];
        float w01 = src[(co * cin + ci0 + 1) * 27 + kk];
        float w10 = src[(co * cin + ci0 + 8) * 27 + kk];
        float w11 = src[(co * cin + ci0 + 9) * 27 + kk];
        uint32_t b0h, b0l, b1h, b1l;
        split_pack_bf16(w00, w01, b0h, b0l);
        split_pack_bf16(w10, w11, b1h, b1l);
        twt[i2] = make_float4(__uint_as_float(b0h), __uint_as_float(b1h),
                              __uint_as_float(b0l), __uint_as_float(b1l));
    }
}

// ----------------------------------------------------------------------------
// mask dtype probe (mode 0=u8 bool, 1=i32 bool, 2=f32, 3=bf16)
// ----------------------------------------------------------------------------
__global__ void probe_k(const unsigned char* __restrict__ b) {
    __shared__ int s_off1, s_big;
    if (threadIdx.x == 0) { s_off1 = 0; s_big = 0; }
    __syncthreads();
    int off1 = 0, big = 0;
    for (int i = threadIdx.x; i < 16384; i += blockDim.x) {
        unsigned char b0 = b[4 * i + 0], b1 = b[4 * i + 1];
        unsigned char b2 = b[4 * i + 2], b3 = b[4 * i + 3];
        if (b1) off1++;
        if (b0 > 1 || b1 > 1 || b2 > 1 || b3 > 1) big++;
    }
    atomicAdd(&s_off1, off1);
    atomicAdd(&s_big, big);
    __syncthreads();
    if (threadIdx.x == 0)
        g_mmode = (s_big == 0) ? ((s_off1 > 0) ? 0 : 1) : ((s_off1 > 0) ? 3 : 2);
}

__device__ __forceinline__ float mask_at(const unsigned char* b, int v, int mode) {
    if (mode == 0) return b[v] ? 1.f : 0.f;
    if (mode == 1) return ((const int*)b)[v] ? 1.f : 0.f;
    if (mode == 2) return (((const float*)b)[v] != 0.f) ? 1.f : 0.f;
    return (__bfloat162float(((const __nv_bfloat16*)b)[v]) != 0.f) ? 1.f : 0.f;
}

__global__ void premask_k(const float* __restrict__ x, const unsigned char* __restrict__ mb,
                          float* __restrict__ xm, float* __restrict__ m0) {
    int v = blockIdx.x * blockDim.x + threadIdx.x;
    if (v >= N0) return;
    int mode = g_mmode;
    float m = mask_at(mb, v, mode);
    m0[v] = m;
    int xx = v & 63, yy = (v >> 6) & 63, zz = v >> 12;
    int pidx = ((zz + 1) * PD0 + (yy + 1)) * PD0 + (xx + 1);
#pragma unroll
    for (int ci = 0; ci < 16; ci++) xm[ci * PD0_3 + pidx] = x[ci * N0 + v] * m;
}

template <int DIN>
__global__ void down_k(const float* __restrict__ mi, float* __restrict__ mo) {
    constexpr int DOUT = DIN / 2;
    int id = blockIdx.x * blockDim.x + threadIdx.x;
    if (id >= DOUT * DOUT * DOUT) return;
    int x = id % DOUT, y = (id / DOUT) % DOUT, z = id / (DOUT * DOUT);
    float m = 0.f;
#pragma unroll
    for (int dz = -1; dz <= 1; dz++) {
        int zz = 2 * z + dz; if ((unsigned)zz >= DIN) continue;
#pragma unroll
        for (int dy = -1; dy <= 1; dy++) {
            int yy = 2 * y + dy; if ((unsigned)yy >= DIN) continue;
#pragma unroll
            for (int dx = -1; dx <= 1; dx++) {
                int xx = 2 * x + dx; if ((unsigned)xx >= DIN) continue;
                m = fmaxf(m, mi[(zz * DIN + yy) * DIN + xx]);
            }
        }
    }
    mo[id] = m;
}

// ----------------------------------------------------------------------------
// bf16 tensor-core stride-1 conv: 3xBF16 on m16n8k16, fused BN epilogue.
// grid = (COUT/NCH, DIN/YR, DIN); YR = 64/DIN; warp = one 16-voxel m-tile.
// ----------------------------------------------------------------------------
template <int CIN, int COUT, int DIN, int NCH>
__global__ __launch_bounds__(128) void tconv_k(const float* __restrict__ in,
                                               const float4* __restrict__ wb,
                                               const float* __restrict__ bnf,
                                               const float* __restrict__ mask,
                                               float* __restrict__ out) {
    constexpr int PDI = DIN + 2;
    constexpr int PDI3 = PDI * PDI * PDI;
    constexpr int PDO3 = PDI3;
    constexpr int TPR = DIN / 16;
    constexpr int YR = 64 / DIN;
    constexpr int NT = NCH / 8;
    constexpr int CS16 = CIN / 16;
    constexpr int NTT = COUT / 8;

    const int warp = threadIdx.x >> 5, lane = threadIdx.x & 31;
    const int gid = lane >> 2, tg = lane & 3;
    const int nc = blockIdx.x;
    const int z = blockIdx.z;
    const int ym = blockIdx.y * YR + warp / TPR;
    const int xt = (warp % TPR) * 16;

    float chi[NT][4], cco[NT][4];
#pragma unroll
    for (int t = 0; t < NT; t++)
#pragma unroll
        for (int j = 0; j < 4; j++) { chi[t][j] = 0.f; cco[t][j] = 0.f; }

    const float* inb = in + 2 * tg * PDI3;
    const float4* bp = wb + nc * NT * 32 + lane;

#pragma unroll 1
    for (int dz = 0; dz < 3; dz++) {
#pragma unroll
        for (int dy = 0; dy < 3; dy++) {
            const float* rp = inb + ((z + dz) * PDI + (ym + dy)) * PDI + xt + gid;
#pragma unroll
            for (int dx = 0; dx < 3; dx++) {
                const float* ap = rp + dx;
#pragma unroll
                for (int s = 0; s < CS16; s++) {
                    float v00 = __ldg(ap);
                    float v01 = __ldg(ap + PDI3);
                    float v10 = __ldg(ap + 8);
                    float v11 = __ldg(ap + PDI3 + 8);
                    float v20 = __ldg(ap + 8 * PDI3);
                    float v21 = __ldg(ap + 9 * PDI3);
                    float v30 = __ldg(ap + 8 * PDI3 + 8);
                    float v31 = __ldg(ap + 9 * PDI3 + 8);
                    uint32_t ah[4], al[4];
                    split_pack_bf16(v00, v01, ah[0], al[0]);
                    split_pack_bf16(v10, v11, ah[1], al[1]);
                    split_pack_bf16(v20, v21, ah[2], al[2]);
                    split_pack_bf16(v30, v31, ah[3], al[3]);
#pragma unroll
                    for (int t = 0; t < NT; t++) {
                        float4 bb = __ldg(bp + t * 32);
                        uint32_t bh0 = __float_as_uint(bb.x), bh1 = __float_as_uint(bb.y);
                        uint32_t bl0 = __float_as_uint(bb.z), bl1 = __float_as_uint(bb.w);
                        mma_bf16(chi[t], ah, bh0, bh1);
                        mma_bf16(cco[t], ah, bl0, bl1);
                        mma_bf16(cco[t], al, bh0, bh1);
                    }
                    ap += 16 * PDI3;
                    bp += NTT * 32;
                }
            }
        }
    }

    int voxu = (z * DIN + ym) * DIN + xt;
    float mv0 = mask[voxu + gid];
    float mv1 = mask[voxu + gid + 8];
    int pv = ((z + 1) * PDI + (ym + 1)) * PDI + (xt + 1) + gid;
#pragma unroll
    for (int t = 0; t < NT; t++) {
        int c0 = nc * NCH + t * 8 + 2 * tg;
        float4 b4 = *reinterpret_cast<const float4*>(bnf + 2 * c0);
        float* o0 = out + c0 * PDO3 + pv;
        float* o1 = o0 + PDO3;
        float r0 = chi[t][0] + cco[t][0];
        float r1 = chi[t][1] + cco[t][1];
        float r2 = chi[t][2] + cco[t][2];
        float r3 = chi[t][3] + cco[t][3];
        o0[0] = fmaxf(fmaf(b4.x, r0, b4.y), 0.f) * mv0;
        o1[0] = fmaxf(fmaf(b4.z, r1, b4.w), 0.f) * mv0;
        o0[8] = fmaxf(fmaf(b4.x, r2, b4.y), 0.f) * mv1;
        o1[8] = fmaxf(fmaf(b4.z, r3, b4.w), 0.f) * mv1;
    }
}

// ----------------------------------------------------------------------------
// scalar conv (v7) — stride-2 layers only
// ----------------------------------------------------------------------------
template <int CIN, int COUT, int STRIDE, int DIN, int SPLIT, int XT, int YT, int CH, bool FUSE>
__global__ __launch_bounds__(128, 4) void conv_k(const float* __restrict__ in,
                                                 const float* __restrict__ wt,
                                                 const float* __restrict__ bnf,
                                                 const float* __restrict__ mask,
                                                 float* __restrict__ out) {
    constexpr int DOUT = DIN / STRIDE;
    constexpr int PDI = DIN + 2;
    constexpr int PDI3 = PDI * PDI * PDI;
    constexpr int PDO = DOUT + 2;
    constexpr int PDO3 = PDO * PDO * PDO;
    constexpr int CHUNKS = COUT / CH;
    constexpr int CIB = CIN / SPLIT;
    constexpr int W = (XT - 1) * STRIDE + 3;
    constexpr int ROWS = (YT - 1) * STRIDE + 3;

    int tx = threadIdx.x, ty = threadIdx.y;
    int chunk = blockIdx.x % CHUNKS;
    int split = blockIdx.x / CHUNKS;
    int cb = chunk * CH;
    int y0 = (blockIdx.y * blockDim.y + ty) * YT;
    int z = blockIdx.z * blockDim.z + threadIdx.z;
    int x0 = XT * tx;

    float acc[YT * XT * CH];
#pragma unroll
    for (int i = 0; i < YT * XT * CH; i++) acc[i] = 0.f;

    const float* base = in + split * CIB * PDI3
                        + (z * STRIDE * PDI + y0 * STRIDE) * PDI + x0 * STRIDE;
    const float* wp = wt + (split * CIB * 27) * COUT + cb;

    for (int ci = 0; ci < CIB; ci++) {
#pragma unroll
        for (int dz = 0; dz < 3; dz++) {
            float v[ROWS][W];
#pragma unroll
            for (int r = 0; r < ROWS; r++) {
                const float* rp = base + (dz * PDI + r) * PDI;
                const float2* rp2 = reinterpret_cast<const float2*>(rp);
#pragma unroll
                for (int i = 0; i < W / 2; i++) {
                    float2 t = __ldg(rp2 + i);
                    v[r][2 * i] = t.x;
                    v[r][2 * i + 1] = t.y;
                }
                if (W & 1) v[r][W - 1] = __ldg(rp + W - 1);
            }
#pragma unroll
            for (int dy = 0; dy < 3; dy++)
#pragma unroll
                for (int dx = 0; dx < 3; dx++) {
                    const int k = (dz * 3 + dy) * 3 + dx;
                    const float4* w4 = reinterpret_cast<const float4*>(wp + k * COUT);
#pragma unroll
                    for (int j = 0; j < CH / 4; j++) {
                        float4 ww = __ldg(w4 + j);
#pragma unroll
                        for (int yt = 0; yt < YT; yt++)
#pragma unroll
                            for (int xt = 0; xt < XT; xt++) {
                                float a = v[yt * STRIDE + dy][xt * STRIDE + dx];
                                int o = (yt * XT + xt) * CH + 4 * j;
                                acc[o + 0] = fmaf(a, ww.x, acc[o + 0]);
                                acc[o + 1] = fmaf(a, ww.y, acc[o + 1]);
                                acc[o + 2] = fmaf(a, ww.z, acc[o + 2]);
                                acc[o + 3] = fmaf(a, ww.w, acc[o + 3]);
                            }
                    }
                }
        }
        base += PDI3;
        wp += 27 * COUT;
    }

    if (FUSE) {
#pragma unroll
        for (int yt = 0; yt < YT; yt++) {
            int voxu = (z * DOUT + y0 + yt) * DOUT + x0;
            float mm[XT];
#pragma unroll
            for (int xt = 0; xt < XT; xt++) mm[xt] = mask[voxu + xt];
            int pvox = ((z + 1) * PDO + (y0 + yt + 1)) * PDO + (x0 + 1);
#pragma unroll
            for (int i = 0; i < CH; i++) {
                int c = cb + i;
                float s = __ldg(bnf + 2 * c);
                float t = __ldg(bnf + 2 * c + 1);
#pragma unroll
                for (int xt = 0; xt < XT; xt++)
                    out[c * PDO3 + pvox + xt] =
                        fmaxf(fmaf(s, acc[(yt * XT + xt) * CH + i], t), 0.f) * mm[xt];
            }
        }
    } else {
        constexpr int N = DOUT * DOUT * DOUT;
#pragma unroll
        for (int yt = 0; yt < YT; yt++) {
            int vox = (z * DOUT + y0 + yt) * DOUT + x0;
#pragma unroll
            for (int i = 0; i < CH; i++) {
                int c = cb + i;
#pragma unroll
                for (int xt = 0; xt < XT; xt++)
                    out[(split * COUT + c) * N + vox + xt] = acc[(yt * XT + xt) * CH + i];
            }
        }
    }
}

// epilogue for split convs
template <int COUT, int DOUT, int SPLIT>
__global__ void epi_k(const float* __restrict__ part, const float* __restrict__ bnf,
                      const float* __restrict__ mask, float* __restrict__ out) {
    constexpr int N = DOUT * DOUT * DOUT;
    constexpr int PDO = DOUT + 2;
    constexpr int PDO3 = PDO * PDO * PDO;
    int id = blockIdx.x * blockDim.x + threadIdx.x;
    if (id >= COUT * N) return;
    int vox = id % N, c = id / N;
    float a = 0.f;
#pragma unroll
    for (int s = 0; s < SPLIT; s++) a += part[(s * COUT + c) * N + vox];
    float sc = __ldg(bnf + 2 * c), t = __ldg(bnf + 2 * c + 1);
    int x = vox % DOUT, y = (vox / DOUT) % DOUT, z = vox / (DOUT * DOUT);
    out[c * PDO3 + ((z + 1) * PDO + (y + 1)) * PDO + (x + 1)] =
        fmaxf(fmaf(sc, a, t), 0.f) * mask[vox];
}

// ----------------------------------------------------------------------------
// triplane means + sampler
// ----------------------------------------------------------------------------
__global__ void planes_k(const float* __restrict__ f, float* __restrict__ pl) {
    int id = blockIdx.x * blockDim.x + threadIdx.x;
    if (id >= 3 * 16 * 16 * 128) return;
    int c = id & 127;
    int rem = id >> 7;
    int b = rem & 15;
    int a = (rem >> 4) & 15;
    int t = rem >> 8;
    const float* fc = f + c * PD2_3;
    float s = 0.f;
    if (t == 0) {
#pragma unroll
        for (int z = 0; z < 16; z++) s += fc[((z + 1) * PD2 + (a + 1)) * PD2 + (b + 1)];
    } else if (t == 1) {
#pragma unroll
        for (int xx = 0; xx < 16; xx++) s += fc[((a + 1) * PD2 + (b + 1)) * PD2 + (xx + 1)];
    } else {
#pragma unroll
        for (int yy = 0; yy < 16; yy++) s += fc[((a + 1) * PD2 + (yy + 1)) * PD2 + (b + 1)];
    }
    pl[t * (16 * 16 * 128) + (a * 16 + b) * 128 + c] = s * (1.f / 16.f);
}

__device__ __forceinline__ float samp2d(const float* __restrict__ img, float gx, float gy, int c) {
    float ix = (gx + 1.f) * 0.5f * 15.f;
    float iy = (gy + 1.f) * 0.5f * 15.f;
    float x0f = floorf(ix), y0f = floorf(iy);
    int x0 = (int)x0f, y0 = (int)y0f;
    float wx = ix - x0f, wy = iy - y0f;
    float r = 0.f;
#pragma unroll
    for (int dy = 0; dy < 2; dy++)
#pragma unroll
        for (int dx = 0; dx < 2; dx++) {
            int xx = x0 + dx, yy = y0 + dy;
            float w = (dy ? wy : 1.f - wy) * (dx ? wx : 1.f - wx);
            bool ok = ((unsigned)xx < 16u) && ((unsigned)yy < 16u);
            int xc = min(max(xx, 0), 15), yc = min(max(yy, 0), 15);
            float v = __ldg(img + (yc * 16 + xc) * 128 + c);
            r += v * (ok ? w : 0.f);
        }
    return r;
}

__global__ void sample_k(const float* __restrict__ coords, const float* __restrict__ planes,
                         float* __restrict__ out) {
    constexpr int PTS = 16;
    int c = threadIdx.x;  // 128
    int p0 = blockIdx.x * PTS;
#pragma unroll 1
    for (int i = 0; i < PTS; i++) {
        int p = p0 + i;
        float c0 = __ldg(coords + 3 * p + 0);
        float c1 = __ldg(coords + 3 * p + 1);
        float c2 = __ldg(coords + 3 * p + 2);
        float s = samp2d(planes + 0 * (16 * 16 * 128), c0, c1, c)
                + samp2d(planes + 1 * (16 * 16 * 128), c1, c2, c)
                + samp2d(planes + 2 * (16 * 16 * 128), c0, c2, c);
        out[(size_t)p * 128 + c] = s;
    }
}

// ----------------------------------------------------------------------------
// launch — launch #4 is tconv0a (ncu target)
// ----------------------------------------------------------------------------
extern "C" void kernel_launch(void* const* d_in, const int* in_sizes, int n_in,
                              void* d_out, int out_size) {
    const float* x = (const float*)d_in[0];
    const unsigned char* mask = (const unsigned char*)d_in[1];
    const float* coords = (const float*)d_in[2];
    const float* w0a = (const float*)d_in[3];  const float* bn0a = (const float*)d_in[4];
    const float* w0b = (const float*)d_in[5];  const float* bn0b = (const float*)d_in[6];
    const float* wd0 = (const float*)d_in[7];  const float* bnd0 = (const float*)d_in[8];
    const float* w1a = (const float*)d_in[9];  const float* bn1a = (const float*)d_in[10];
    const float* w1b = (const float*)d_in[11]; const float* bn1b = (const float*)d_in[12];
    const float* wd1 = (const float*)d_in[13]; const float* bnd1 = (const float*)d_in[14];
    const float* w2a = (const float*)d_in[15]; const float* bn2a = (const float*)d_in[16];
    const float* w2b = (const float*)d_in[17]; const float* bn2b = (const float*)d_in[18];
    const float* w2c = (const float*)d_in[19]; const float* bn2c = (const float*)d_in[20];

    float *xm, *A0, *B0, *A1, *B1, *A2, *B2, *part, *m0, *m1, *m2, *wt, *bnf, *pl;
    float4* twt;
    cudaGetSymbolAddress((void**)&xm, g_xm);
    cudaGetSymbolAddress((void**)&A0, g_A0);
    cudaGetSymbolAddress((void**)&B0, g_B0);
    cudaGetSymbolAddress((void**)&A1, g_A1);
    cudaGetSymbolAddress((void**)&B1, g_B1);
    cudaGetSymbolAddress((void**)&A2, g_A2);
    cudaGetSymbolAddress((void**)&B2, g_B2);
    cudaGetSymbolAddress((void**)&part, g_part);
    cudaGetSymbolAddress((void**)&m0, g_m0);
    cudaGetSymbolAddress((void**)&m1, g_m1);
    cudaGetSymbolAddress((void**)&m2, g_m2);
    cudaGetSymbolAddress((void**)&wt, g_wt);
    cudaGetSymbolAddress((void**)&twt, g_twt);
    cudaGetSymbolAddress((void**)&bnf, g_bnf);
    cudaGetSymbolAddress((void**)&pl, g_planes);

    // 1-3: probe, merged prep, premask
    probe_k<<<1, 256>>>(mask);
    int prtot = WT_TOTAL + 736 + TB_TOTAL;
    prep_k<<<(prtot + 255) / 256, 256>>>(w0a, w0b, wd0, w1a, w1b, wd1, w2a, w2b, w2c,
                                         bn0a, bn0b, bnd0, bn1a, bn1b, bnd1, bn2a, bn2b, bn2c,
                                         wt, bnf, twt);
    premask_k<<<(N0 + 255) / 256, 256>>>(x, mask, xm, m0);

    // 4-6: bf16 tensor conv0a (ncu target), conv0b, scalar convd0
    tconv_k<16, 32, 64, 32><<<dim3(1, 64, 64), 128>>>(xm, twt + TB_W0A, bnf + OB_0A, m0, A0);
    tconv_k<32, 32, 64, 32><<<dim3(1, 64, 64), 128>>>(A0, twt + TB_W0B, bnf + OB_0B, m0, B0);
    conv_k<32, 32, 2, 64, 2, 2, 1, 16, false><<<dim3(4, 4, 32), dim3(16, 8)>>>(B0, wt + O_WD0, nullptr, nullptr, part);

    // 7-9: mask downsamples + epi_d0
    down_k<64><<<(N1 + 255) / 256, 256>>>(m0, m1);
    epi_k<32, 32, 2><<<(32 * N1 + 255) / 256, 256>>>(part, bnf + OB_D0, m1, A1);
    down_k<32><<<(N2 + 255) / 256, 256>>>(m1, m2);

    // 10-13: stage 1 @32^3 — bf16 tensor + scalar downsample 1
    tconv_k<32, 64, 32, 32><<<dim3(2, 16, 32), 128>>>(A1, twt + TB_W1A, bnf + OB_1A, m1, B1);
    tconv_k<64, 64, 32, 32><<<dim3(2, 16, 32), 128>>>(B1, twt + TB_W1B, bnf + OB_1B, m1, A1);
    conv_k<64, 128, 2, 32, 4, 2, 1, 16, false><<<dim3(32, 1, 16), dim3(8, 16)>>>(A1, wt + O_WD1, nullptr, nullptr, part);
    epi_k<128, 16, 4><<<(128 * N2 + 255) / 256, 256>>>(part, bnf + OB_D1, m2, A2);

    // 14-16: stage 2 @16^3 — bf16 tensor (fused epilogues, no split/epi)
    tconv_k<128, 128, 16, 16><<<dim3(8, 4, 16), 128>>>(A2, twt + TB_W2A, bnf + OB_2A, m2, B2);
    tconv_k<128, 128, 16, 16><<<dim3(8, 4, 16), 128>>>(B2, twt + TB_W2B, bnf + OB_2B, m2, A2);
    tconv_k<128, 128, 16, 16><<<dim3(8, 4, 16), 128>>>(A2, twt + TB_W2C, bnf + OB_2C, m2, B2);

    // 17-18: triplane + sample
    planes_k<<<(3 * 16 * 16 * 128 + 255) / 256, 256>>>(B2, pl);
    sample_k<<<NPTS / 16, 128>>>(coords, pl, (float*)d_out);
}